// round 9
// baseline (speedup 1.0000x reference)
#include <cuda_runtime.h>
#include <cuda_fp16.h>
#include <math.h>
#include <stdint.h>

#define T_TOK 4096
#define CDIM  1024
#define HDIM  4096
#define EDIM  8

// ---------------- device scratch (allocation-free) ----------------
__device__ float  g_gate_sums[EDIM];
__device__ int    g_cnt[EDIM];
__device__ int    g_bucket_tok[EDIM * T_TOK];
__device__ int    g_pair_slot[T_TOK * 2];
__device__ float  g_pair_gate[T_TOK * 2];
__device__ __half g_Ah [(size_t)EDIM * T_TOK * CDIM];   // gathered x, fp16
__device__ __half g_Hh [(size_t)EDIM * T_TOK * HDIM];   // gelu(h), fp16
__device__ __half g_W1t[(size_t)EDIM * HDIM  * CDIM];   // w1^T fp16 [E][H][C]
__device__ __half g_W2t[(size_t)EDIM * CDIM  * HDIM];   // w2^T fp16 [E][C][H]
__device__ float  g_Y  [(size_t)EDIM * T_TOK * CDIM];

// ---------------- helpers ----------------
__device__ __forceinline__ uint32_t smem_u32(const void* p) {
    uint32_t a;
    asm("{ .reg .u64 t; cvta.to.shared.u64 t, %1; cvt.u32.u64 %0, t; }" : "=r"(a) : "l"(p));
    return a;
}
__device__ __forceinline__ void cp_async16(uint32_t dst, const void* src) {
    asm volatile("cp.async.cg.shared.global [%0], [%1], 16;\n" :: "r"(dst), "l"(src));
}
#define CP_COMMIT() asm volatile("cp.async.commit_group;" ::: "memory")
#define CP_WAIT1()  asm volatile("cp.async.wait_group 1;" ::: "memory")

__device__ __forceinline__ void ldmx4(uint32_t& r0, uint32_t& r1, uint32_t& r2, uint32_t& r3,
                                      uint32_t addr) {
    asm volatile("ldmatrix.sync.aligned.m8n8.x4.shared.b16 {%0,%1,%2,%3}, [%4];"
                 : "=r"(r0), "=r"(r1), "=r"(r2), "=r"(r3) : "r"(addr));
}
__device__ __forceinline__ void mma16816(float* d, const uint32_t* a, uint32_t b0, uint32_t b1) {
    asm volatile("mma.sync.aligned.m16n8k16.row.col.f32.f16.f16.f32 "
                 "{%0,%1,%2,%3}, {%4,%5,%6,%7}, {%8,%9}, {%0,%1,%2,%3};"
                 : "+f"(d[0]), "+f"(d[1]), "+f"(d[2]), "+f"(d[3])
                 : "r"(a[0]), "r"(a[1]), "r"(a[2]), "r"(a[3]), "r"(b0), "r"(b1));
}
// byte offset in a [rows][32 halves] tile; 16B chunk swizzle: c ^= (r>>1)&3
__device__ __forceinline__ uint32_t sma(int r, int c) {
    return (uint32_t)(((r << 2) | (c ^ ((r >> 1) & 3))) << 4);
}

// ---------------------------------------------------------------------------
__global__ void init_kernel() {
    int i = threadIdx.x;
    if (i < EDIM) { g_gate_sums[i] = 0.0f; g_cnt[i] = 0; }
}

__global__ void gate_kernel(const float* __restrict__ x,
                            const float* __restrict__ gumbel,
                            const float* __restrict__ gw,
                            const float* __restrict__ gb) {
    const int t = blockIdx.x, tid = threadIdx.x;
    float acc[EDIM];
#pragma unroll
    for (int e = 0; e < EDIM; e++) acc[e] = 0.0f;
    const float* xr = x + (size_t)t * CDIM;
    for (int i = tid; i < CDIM; i += 128) {
        float xv = xr[i];
#pragma unroll
        for (int e = 0; e < EDIM; e++) acc[e] += xv * gw[i * EDIM + e];
    }
    __shared__ float red[128][EDIM];
#pragma unroll
    for (int e = 0; e < EDIM; e++) red[tid][e] = acc[e];
    __syncthreads();
    for (int s = 64; s > 0; s >>= 1) {
        if (tid < s) {
#pragma unroll
            for (int e = 0; e < EDIM; e++) red[tid][e] += red[tid + s][e];
        }
        __syncthreads();
    }
    if (tid == 0) {
        float l[EDIM]; float mx = -1e30f;
#pragma unroll
        for (int e = 0; e < EDIM; e++) {
            l[e] = red[0][e] + gb[e] + gumbel[t * EDIM + e];
            mx = fmaxf(mx, l[e]);
        }
        float sum = 0.0f;
#pragma unroll
        for (int e = 0; e < EDIM; e++) { l[e] = expf(l[e] - mx); sum += l[e]; }
        float inv = 1.0f / sum;
        float g[EDIM];
#pragma unroll
        for (int e = 0; e < EDIM; e++) { g[e] = l[e] * inv; atomicAdd(&g_gate_sums[e], g[e]); }
        int i0 = 0;
#pragma unroll
        for (int e = 1; e < EDIM; e++) if (g[e] > g[i0]) i0 = e;
        int i1 = (i0 == 0) ? 1 : 0;
#pragma unroll
        for (int e = 0; e < EDIM; e++) if (e != i0 && g[e] > g[i1]) i1 = e;
        int p0 = atomicAdd(&g_cnt[i0], 1);
        g_bucket_tok[i0 * T_TOK + p0] = t;
        g_pair_slot[t * 2 + 0] = i0 * T_TOK + p0;
        g_pair_gate[t * 2 + 0] = g[i0];
        int p1 = atomicAdd(&g_cnt[i1], 1);
        g_bucket_tok[i1 * T_TOK + p1] = t;
        g_pair_slot[t * 2 + 1] = i1 * T_TOK + p1;
        g_pair_gate[t * 2 + 1] = g[i1];
    }
}

// gather x rows per expert slot -> fp16 (zero-pad to 256-row boundary)
__global__ void convert_x_kernel(const float* __restrict__ x) {
    const int e = blockIdx.y, s = blockIdx.x;
    const int cnt = g_cnt[e];
    const int padded = (cnt + 255) & ~255;
    if (s >= padded) return;
    __half* dst = g_Ah + (size_t)(e * T_TOK + s) * CDIM;
    const int t = threadIdx.x;  // 256 threads x 4 floats
    if (s < cnt) {
        int tok = g_bucket_tok[e * T_TOK + s];
        float4 v = ((const float4*)(x + (size_t)tok * CDIM))[t];
        ((__half2*)dst)[2 * t + 0] = __floats2half2_rn(v.x, v.y);
        ((__half2*)dst)[2 * t + 1] = __floats2half2_rn(v.z, v.w);
    } else {
        __half2 z = __floats2half2_rn(0.f, 0.f);
        ((__half2*)dst)[2 * t + 0] = z;
        ((__half2*)dst)[2 * t + 1] = z;
    }
}

// transpose + fp16 convert: in [E][A][Bd] fp32 -> out [E][Bd][A] fp16
// Tile: 64 (a) x 32 (b); vectorized half2 stores.
__global__ void convert_w_kernel(const float* __restrict__ W, int A, int Bd, int which) {
    __shared__ float s[64][33];
    const int e = blockIdx.z;
    const int a0 = blockIdx.y * 64, b0 = blockIdx.x * 32;
    const int t = threadIdx.x;  // 256
    const float* Wp = W + (size_t)e * A * Bd;
    __half* Wt = (which ? g_W2t : g_W1t) + (size_t)e * A * Bd;
    {
        const int col = t & 31;
        const int r0 = t >> 5;          // 0..7
#pragma unroll
        for (int i = 0; i < 8; i++) {
            int r = r0 + i * 8;
            s[r][col] = Wp[(size_t)(a0 + r) * Bd + b0 + col];
        }
    }
    __syncthreads();
    {
        const int col2 = t & 31;
        const int bb0  = t >> 5;
#pragma unroll
        for (int j = 0; j < 4; j++) {
            int b = bb0 + j * 8;
            __half2 hv = __floats2half2_rn(s[2 * col2][b], s[2 * col2 + 1][b]);
            *(__half2*)(Wt + (size_t)(b0 + b) * A + a0 + 2 * col2) = hv;
        }
    }
}

// ---------------------------------------------------------------------------
// HMMA grouped GEMM: BM=256, BN=128, BK=32, 256 threads (8 warps as 4m x 2n, 64x64 tiles).
#define GEMM_SMEM (3 * 24576)
template<bool GELU, int NK>   // NK = K/32
__global__ __launch_bounds__(256, 1) void gemm_hmma(const float* __restrict__ bias) {
    const int e = blockIdx.z;
    const int cnt = g_cnt[e];
    const int m0 = blockIdx.y * 256;
    if (m0 >= cnt) return;
    const int n0 = blockIdx.x * 128;

    const int K    = GELU ? CDIM : HDIM;   // row stride (halves) for A and B
    const int NTOT = GELU ? HDIM : CDIM;
    const __half* __restrict__ abase = GELU ? g_Ah  : g_Hh;
    const __half* __restrict__ bbase = GELU ? g_W1t : g_W2t;

    extern __shared__ __align__(16) char smraw[];
    // per stage: A 256x32 halves (16384B) then B 128x32 (8192B)
    const uint32_t sb = smem_u32(smraw);

    const int tid  = threadIdx.x;
    const int lane = tid & 31;
    const int w    = tid >> 5;
    const int wm   = w & 3;        // 4 m-groups of 64
    const int wn   = w >> 2;       // 2 n-groups of 64

    const __half* A0 = abase + (size_t)(e * T_TOK + m0) * K;
    const __half* B0 = bbase + ((size_t)e * NTOT + n0) * K;

    float acc[4][8][4];
#pragma unroll
    for (int i = 0; i < 4; i++)
#pragma unroll
        for (int j = 0; j < 8; j++)
#pragma unroll
            for (int q = 0; q < 4; q++) acc[i][j][q] = 0.0f;

    auto load_stage = [&](int kc) {
        const int st = kc % 3;
        const __half* ap = A0 + kc * 32;
        const __half* bp = B0 + kc * 32;
        const uint32_t aS = sb + st * 24576;
        const uint32_t bS = aS + 16384;
#pragma unroll
        for (int h = 0; h < 4; h++) {       // A: 1024 16B-chunks
            int id = tid + h * 256;
            int row = id >> 2, c = id & 3;
            cp_async16(aS + sma(row, c), ap + (size_t)row * K + c * 8);
        }
#pragma unroll
        for (int h = 0; h < 2; h++) {       // B: 512 chunks
            int id = tid + h * 256;
            int row = id >> 2, c = id & 3;
            cp_async16(bS + sma(row, c), bp + (size_t)row * K + c * 8);
        }
    };

    load_stage(0); CP_COMMIT();
    load_stage(1); CP_COMMIT();

#pragma unroll 1
    for (int kc = 0; kc < NK; kc++) {
        const int s = kc % 3;
        CP_WAIT1();
        __syncthreads();
        if (kc + 2 < NK) load_stage(kc + 2);
        CP_COMMIT();

        const uint32_t aS = sb + s * 24576;
        const uint32_t bS = aS + 16384;
#pragma unroll
        for (int ks = 0; ks < 2; ks++) {
            uint32_t afr[4][4];
#pragma unroll
            for (int mi = 0; mi < 4; mi++) {
                int row = wm * 64 + mi * 16 + ((lane >> 3) & 1) * 8 + (lane & 7);
                int ch  = ks * 2 + (lane >> 4);
                ldmx4(afr[mi][0], afr[mi][1], afr[mi][2], afr[mi][3], aS + sma(row, ch));
            }
            uint32_t bfr[4][4];
#pragma unroll
            for (int nj = 0; nj < 4; nj++) {
                int row = wn * 64 + nj * 16 + (lane >> 4) * 8 + (lane & 7);
                int ch  = ks * 2 + ((lane >> 3) & 1);
                ldmx4(bfr[nj][0], bfr[nj][1], bfr[nj][2], bfr[nj][3], bS + sma(row, ch));
            }
#pragma unroll
            for (int mi = 0; mi < 4; mi++)
#pragma unroll
                for (int nj = 0; nj < 4; nj++) {
                    mma16816(acc[mi][nj * 2 + 0], afr[mi], bfr[nj][0], bfr[nj][1]);
                    mma16816(acc[mi][nj * 2 + 1], afr[mi], bfr[nj][2], bfr[nj][3]);
                }
        }
        __syncthreads();
    }

    // ---- epilogue ----
    const int r0l = lane >> 2;
    const int c0l = (lane & 3) * 2;
#pragma unroll
    for (int mi = 0; mi < 4; mi++) {
#pragma unroll
        for (int ni = 0; ni < 8; ni++) {
            int gc = n0 + wn * 64 + ni * 8 + c0l;
            float bv0 = __ldg(&bias[(size_t)e * NTOT + gc]);
            float bv1 = __ldg(&bias[(size_t)e * NTOT + gc + 1]);
#pragma unroll
            for (int hh = 0; hh < 2; hh++) {
                int lrow = m0 + wm * 64 + mi * 16 + r0l + hh * 8;
                size_t slot = (size_t)(e * T_TOK) + lrow;
                float v0 = acc[mi][ni][hh * 2 + 0] + bv0;
                float v1 = acc[mi][ni][hh * 2 + 1] + bv1;
                if (GELU) {
                    float q0 = 0.5f * v0 * (1.0f + erff(v0 * 0.70710678118654752f));
                    float q1 = 0.5f * v1 * (1.0f + erff(v1 * 0.70710678118654752f));
                    *(__half2*)(g_Hh + slot * HDIM + gc) = __floats2half2_rn(q0, q1);
                } else {
                    *(float2*)(g_Y + slot * CDIM + gc) = make_float2(v0, v1);
                }
            }
        }
    }
}

// ---------------------------------------------------------------------------
__global__ void combine_kernel(float* __restrict__ out) {
    const int t = blockIdx.x;
    const int cidx = threadIdx.x * 4;
    int   s0 = g_pair_slot[t * 2 + 0];
    int   s1 = g_pair_slot[t * 2 + 1];
    float g0 = g_pair_gate[t * 2 + 0];
    float g1 = g_pair_gate[t * 2 + 1];
    float4 y0 = *reinterpret_cast<const float4*>(&g_Y[(size_t)s0 * CDIM + cidx]);
    float4 y1 = *reinterpret_cast<const float4*>(&g_Y[(size_t)s1 * CDIM + cidx]);
    float4 o;
    o.x = g0 * y0.x + g1 * y1.x;
    o.y = g0 * y0.y + g1 * y1.y;
    o.z = g0 * y0.z + g1 * y1.z;
    o.w = g0 * y0.w + g1 * y1.w;
    *reinterpret_cast<float4*>(&out[(size_t)t * CDIM + cidx]) = o;
}

__global__ void loss_kernel(float* __restrict__ out, int out_size) {
    if (threadIdx.x == 0 && out_size > T_TOK * CDIM) {
        float l = 0.0f;
#pragma unroll
        for (int e = 0; e < EDIM; e++) {
            float m = g_gate_sums[e] / (float)T_TOK;
            l += m * logf(m + 1e-8f);
        }
        out[T_TOK * CDIM] = l;
    }
}

// ---------------------------------------------------------------------------
extern "C" void kernel_launch(void* const* d_in, const int* in_sizes, int n_in,
                              void* d_out, int out_size) {
    const float* x      = (const float*)d_in[0];
    const float* gumbel = (const float*)d_in[1];
    const float* gate_w = (const float*)d_in[2];
    const float* gate_b = (const float*)d_in[3];
    const float* w1     = (const float*)d_in[4];
    const float* b1     = (const float*)d_in[5];
    const float* w2     = (const float*)d_in[6];
    const float* b2     = (const float*)d_in[7];
    float* out = (float*)d_out;

    static bool attr_done = false;
    if (!attr_done) {
        cudaFuncSetAttribute(gemm_hmma<true, 32>,
                             cudaFuncAttributeMaxDynamicSharedMemorySize, GEMM_SMEM);
        cudaFuncSetAttribute(gemm_hmma<false, 128>,
                             cudaFuncAttributeMaxDynamicSharedMemorySize, GEMM_SMEM);
        attr_done = true;
    }

    init_kernel<<<1, 32>>>();
    gate_kernel<<<T_TOK, 128>>>(x, gumbel, gate_w, gate_b);
    convert_x_kernel<<<dim3(T_TOK, EDIM), 256>>>(x);
    convert_w_kernel<<<dim3(HDIM / 32, CDIM / 64, EDIM), 256>>>(w1, CDIM, HDIM, 0);
    convert_w_kernel<<<dim3(CDIM / 32, HDIM / 64, EDIM), 256>>>(w2, HDIM, CDIM, 1);
    gemm_hmma<true, 32><<<dim3(HDIM / 128, T_TOK / 256, EDIM), 256, GEMM_SMEM>>>(b1);
    gemm_hmma<false, 128><<<dim3(CDIM / 128, T_TOK / 256, EDIM), 256, GEMM_SMEM>>>(b2);
    combine_kernel<<<T_TOK, 256>>>(out);
    loss_kernel<<<1, 32>>>(out, out_size);
}

// round 10
// speedup vs baseline: 1.2527x; 1.2527x over previous
#include <cuda_runtime.h>
#include <cuda_fp16.h>
#include <math.h>
#include <stdint.h>

#define T_TOK 4096
#define CDIM  1024
#define HDIM  4096
#define EDIM  8

// ---------------- device scratch (allocation-free) ----------------
__device__ float  g_gate_sums[EDIM];
__device__ int    g_cnt[EDIM];
__device__ int    g_bucket_tok[EDIM * T_TOK];
__device__ int    g_pair_slot[T_TOK * 2];
__device__ float  g_pair_gate[T_TOK * 2];
__device__ __half g_Ah [(size_t)EDIM * T_TOK * CDIM];   // gathered x, fp16
__device__ __half g_Hh [(size_t)EDIM * T_TOK * HDIM];   // gelu(h), fp16
__device__ __half g_W1t[(size_t)EDIM * HDIM  * CDIM];   // w1^T fp16 [E][H][C]
__device__ __half g_W2t[(size_t)EDIM * CDIM  * HDIM];   // w2^T fp16 [E][C][H]
__device__ float  g_Y  [(size_t)EDIM * T_TOK * CDIM];

// ---------------- helpers ----------------
__device__ __forceinline__ uint32_t smem_u32(const void* p) {
    uint32_t a;
    asm("{ .reg .u64 t; cvta.to.shared.u64 t, %1; cvt.u32.u64 %0, t; }" : "=r"(a) : "l"(p));
    return a;
}
__device__ __forceinline__ void cp_async16(uint32_t dst, const void* src) {
    asm volatile("cp.async.cg.shared.global [%0], [%1], 16;\n" :: "r"(dst), "l"(src));
}
#define CP_COMMIT() asm volatile("cp.async.commit_group;" ::: "memory")
#define CP_WAIT1()  asm volatile("cp.async.wait_group 1;" ::: "memory")

__device__ __forceinline__ void ldmx4(uint32_t& r0, uint32_t& r1, uint32_t& r2, uint32_t& r3,
                                      uint32_t addr) {
    asm volatile("ldmatrix.sync.aligned.m8n8.x4.shared.b16 {%0,%1,%2,%3}, [%4];"
                 : "=r"(r0), "=r"(r1), "=r"(r2), "=r"(r3) : "r"(addr));
}
__device__ __forceinline__ void mma16816(float* d, const uint32_t* a, uint32_t b0, uint32_t b1) {
    asm volatile("mma.sync.aligned.m16n8k16.row.col.f32.f16.f16.f32 "
                 "{%0,%1,%2,%3}, {%4,%5,%6,%7}, {%8,%9}, {%0,%1,%2,%3};"
                 : "+f"(d[0]), "+f"(d[1]), "+f"(d[2]), "+f"(d[3])
                 : "r"(a[0]), "r"(a[1]), "r"(a[2]), "r"(a[3]), "r"(b0), "r"(b1));
}
// byte offset in a [rows][64 halves] (128B-row) tile; full SW128 8-phase swizzle
__device__ __forceinline__ uint32_t sma64(int r, int c) {
    return (uint32_t)(((r << 3) | (c ^ (r & 7))) << 4);
}

// ---------------------------------------------------------------------------
__global__ void init_kernel() {
    int i = threadIdx.x;
    if (i < EDIM) { g_gate_sums[i] = 0.0f; g_cnt[i] = 0; }
}

__global__ void gate_kernel(const float* __restrict__ x,
                            const float* __restrict__ gumbel,
                            const float* __restrict__ gw,
                            const float* __restrict__ gb) {
    const int t = blockIdx.x, tid = threadIdx.x;
    float acc[EDIM];
#pragma unroll
    for (int e = 0; e < EDIM; e++) acc[e] = 0.0f;
    const float* xr = x + (size_t)t * CDIM;
    for (int i = tid; i < CDIM; i += 128) {
        float xv = xr[i];
#pragma unroll
        for (int e = 0; e < EDIM; e++) acc[e] += xv * gw[i * EDIM + e];
    }
    __shared__ float red[128][EDIM];
#pragma unroll
    for (int e = 0; e < EDIM; e++) red[tid][e] = acc[e];
    __syncthreads();
    for (int s = 64; s > 0; s >>= 1) {
        if (tid < s) {
#pragma unroll
            for (int e = 0; e < EDIM; e++) red[tid][e] += red[tid + s][e];
        }
        __syncthreads();
    }
    if (tid == 0) {
        float l[EDIM]; float mx = -1e30f;
#pragma unroll
        for (int e = 0; e < EDIM; e++) {
            l[e] = red[0][e] + gb[e] + gumbel[t * EDIM + e];
            mx = fmaxf(mx, l[e]);
        }
        float sum = 0.0f;
#pragma unroll
        for (int e = 0; e < EDIM; e++) { l[e] = expf(l[e] - mx); sum += l[e]; }
        float inv = 1.0f / sum;
        float g[EDIM];
#pragma unroll
        for (int e = 0; e < EDIM; e++) { g[e] = l[e] * inv; atomicAdd(&g_gate_sums[e], g[e]); }
        int i0 = 0;
#pragma unroll
        for (int e = 1; e < EDIM; e++) if (g[e] > g[i0]) i0 = e;
        int i1 = (i0 == 0) ? 1 : 0;
#pragma unroll
        for (int e = 0; e < EDIM; e++) if (e != i0 && g[e] > g[i1]) i1 = e;
        int p0 = atomicAdd(&g_cnt[i0], 1);
        g_bucket_tok[i0 * T_TOK + p0] = t;
        g_pair_slot[t * 2 + 0] = i0 * T_TOK + p0;
        g_pair_gate[t * 2 + 0] = g[i0];
        int p1 = atomicAdd(&g_cnt[i1], 1);
        g_bucket_tok[i1 * T_TOK + p1] = t;
        g_pair_slot[t * 2 + 1] = i1 * T_TOK + p1;
        g_pair_gate[t * 2 + 1] = g[i1];
    }
}

// gather x rows per expert slot -> fp16 (zero-pad to 128-row boundary)
__global__ void convert_x_kernel(const float* __restrict__ x) {
    const int e = blockIdx.y, s = blockIdx.x;
    const int cnt = g_cnt[e];
    const int padded = (cnt + 127) & ~127;
    if (s >= padded) return;
    __half* dst = g_Ah + (size_t)(e * T_TOK + s) * CDIM;
    const int t = threadIdx.x;  // 256 threads x 4 floats
    if (s < cnt) {
        int tok = g_bucket_tok[e * T_TOK + s];
        float4 v = ((const float4*)(x + (size_t)tok * CDIM))[t];
        ((__half2*)dst)[2 * t + 0] = __floats2half2_rn(v.x, v.y);
        ((__half2*)dst)[2 * t + 1] = __floats2half2_rn(v.z, v.w);
    } else {
        __half2 z = __floats2half2_rn(0.f, 0.f);
        ((__half2*)dst)[2 * t + 0] = z;
        ((__half2*)dst)[2 * t + 1] = z;
    }
}

// transpose + fp16 convert: in [E][A][Bd] fp32 -> out [E][Bd][A] fp16
__global__ void convert_w_kernel(const float* __restrict__ W, int A, int Bd, int which) {
    __shared__ float s[64][33];
    const int e = blockIdx.z;
    const int a0 = blockIdx.y * 64, b0 = blockIdx.x * 32;
    const int t = threadIdx.x;  // 256
    const float* Wp = W + (size_t)e * A * Bd;
    __half* Wt = (which ? g_W2t : g_W1t) + (size_t)e * A * Bd;
    {
        const int col = t & 31;
        const int r0 = t >> 5;          // 0..7
#pragma unroll
        for (int i = 0; i < 8; i++) {
            int r = r0 + i * 8;
            s[r][col] = Wp[(size_t)(a0 + r) * Bd + b0 + col];
        }
    }
    __syncthreads();
    {
        const int col2 = t & 31;
        const int bb0  = t >> 5;
#pragma unroll
        for (int j = 0; j < 4; j++) {
            int b = bb0 + j * 8;
            __half2 hv = __floats2half2_rn(s[2 * col2][b], s[2 * col2 + 1][b]);
            *(__half2*)(Wt + (size_t)(b0 + b) * A + a0 + 2 * col2) = hv;
        }
    }
}

// ---------------------------------------------------------------------------
// HMMA grouped GEMM: BM=128, BN=128, BK=64, 128 threads (4 warps, 64x64 tiles).
#define GEMM_SMEM (3 * 32768)
template<bool GELU, int NK>   // NK = K/64
__global__ __launch_bounds__(128, 2) void gemm_hmma(const float* __restrict__ bias) {
    const int e = blockIdx.z;
    const int cnt = g_cnt[e];
    const int m0 = blockIdx.y * 128;
    if (m0 >= cnt) return;
    const int n0 = blockIdx.x * 128;

    const int K    = GELU ? CDIM : HDIM;   // row stride (halves) for A and B
    const int NTOT = GELU ? HDIM : CDIM;
    const __half* __restrict__ abase = GELU ? g_Ah  : g_Hh;
    const __half* __restrict__ bbase = GELU ? g_W1t : g_W2t;

    extern __shared__ __align__(16) char smraw[];
    const uint32_t sb = smem_u32(smraw);
    // per stage: A 128x64 halves (16384B) then B 128x64 (16384B) => 32KB/stage

    const int tid  = threadIdx.x;
    const int lane = tid & 31;
    const int w    = tid >> 5;
    const int wm   = w & 1;        // m-half of 64
    const int wn   = w >> 1;       // n-half of 64

    const __half* A0 = abase + (size_t)(e * T_TOK + m0) * K;
    const __half* B0 = bbase + ((size_t)e * NTOT + n0) * K;

    float acc[4][8][4];
#pragma unroll
    for (int i = 0; i < 4; i++)
#pragma unroll
        for (int j = 0; j < 8; j++)
#pragma unroll
            for (int q = 0; q < 4; q++) acc[i][j][q] = 0.0f;

    auto load_stage = [&](int kc) {
        const int st = kc % 3;
        const __half* ap = A0 + kc * 64;
        const __half* bp = B0 + kc * 64;
        const uint32_t aS = sb + st * 32768;
        const uint32_t bS = aS + 16384;
#pragma unroll
        for (int h = 0; h < 8; h++) {   // A: 1024 16B chunks over 128 threads
            int id = tid + h * 128;
            int row = id >> 3, c = id & 7;
            cp_async16(aS + sma64(row, c), ap + (size_t)row * K + c * 8);
        }
#pragma unroll
        for (int h = 0; h < 8; h++) {   // B: 1024 chunks
            int id = tid + h * 128;
            int row = id >> 3, c = id & 7;
            cp_async16(bS + sma64(row, c), bp + (size_t)row * K + c * 8);
        }
    };

    load_stage(0); CP_COMMIT();
    load_stage(1); CP_COMMIT();

#pragma unroll 1
    for (int kc = 0; kc < NK; kc++) {
        const int s = kc % 3;
        CP_WAIT1();
        __syncthreads();
        if (kc + 2 < NK) load_stage(kc + 2);
        CP_COMMIT();

        const uint32_t aS = sb + s * 32768;
        const uint32_t bS = aS + 16384;
#pragma unroll
        for (int ks = 0; ks < 4; ks++) {
            uint32_t afr[4][4];
#pragma unroll
            for (int mi = 0; mi < 4; mi++) {
                int row = wm * 64 + mi * 16 + ((lane >> 3) & 1) * 8 + (lane & 7);
                int ch  = ks * 2 + (lane >> 4);
                ldmx4(afr[mi][0], afr[mi][1], afr[mi][2], afr[mi][3], aS + sma64(row, ch));
            }
            uint32_t bfr[4][4];
#pragma unroll
            for (int nj = 0; nj < 4; nj++) {
                int row = wn * 64 + nj * 16 + (lane >> 4) * 8 + (lane & 7);
                int ch  = ks * 2 + ((lane >> 3) & 1);
                ldmx4(bfr[nj][0], bfr[nj][1], bfr[nj][2], bfr[nj][3], bS + sma64(row, ch));
            }
#pragma unroll
            for (int mi = 0; mi < 4; mi++)
#pragma unroll
                for (int nj = 0; nj < 4; nj++) {
                    mma16816(acc[mi][nj * 2 + 0], afr[mi], bfr[nj][0], bfr[nj][1]);
                    mma16816(acc[mi][nj * 2 + 1], afr[mi], bfr[nj][2], bfr[nj][3]);
                }
        }
        __syncthreads();
    }

    // ---- epilogue ----
    const int r0l = lane >> 2;
    const int c0l = (lane & 3) * 2;
#pragma unroll
    for (int mi = 0; mi < 4; mi++) {
#pragma unroll
        for (int ni = 0; ni < 8; ni++) {
            int gc = n0 + wn * 64 + ni * 8 + c0l;
            float bv0 = __ldg(&bias[(size_t)e * NTOT + gc]);
            float bv1 = __ldg(&bias[(size_t)e * NTOT + gc + 1]);
#pragma unroll
            for (int hh = 0; hh < 2; hh++) {
                int lrow = m0 + wm * 64 + mi * 16 + r0l + hh * 8;
                size_t slot = (size_t)(e * T_TOK) + lrow;
                float v0 = acc[mi][ni][hh * 2 + 0] + bv0;
                float v1 = acc[mi][ni][hh * 2 + 1] + bv1;
                if (GELU) {
                    float q0 = 0.5f * v0 * (1.0f + erff(v0 * 0.70710678118654752f));
                    float q1 = 0.5f * v1 * (1.0f + erff(v1 * 0.70710678118654752f));
                    *(__half2*)(g_Hh + slot * HDIM + gc) = __floats2half2_rn(q0, q1);
                } else {
                    *(float2*)(g_Y + slot * CDIM + gc) = make_float2(v0, v1);
                }
            }
        }
    }
}

// ---------------------------------------------------------------------------
__global__ void combine_kernel(float* __restrict__ out) {
    const int t = blockIdx.x;
    const int cidx = threadIdx.x * 4;
    int   s0 = g_pair_slot[t * 2 + 0];
    int   s1 = g_pair_slot[t * 2 + 1];
    float g0 = g_pair_gate[t * 2 + 0];
    float g1 = g_pair_gate[t * 2 + 1];
    float4 y0 = *reinterpret_cast<const float4*>(&g_Y[(size_t)s0 * CDIM + cidx]);
    float4 y1 = *reinterpret_cast<const float4*>(&g_Y[(size_t)s1 * CDIM + cidx]);
    float4 o;
    o.x = g0 * y0.x + g1 * y1.x;
    o.y = g0 * y0.y + g1 * y1.y;
    o.z = g0 * y0.z + g1 * y1.z;
    o.w = g0 * y0.w + g1 * y1.w;
    *reinterpret_cast<float4*>(&out[(size_t)t * CDIM + cidx]) = o;
}

__global__ void loss_kernel(float* __restrict__ out, int out_size) {
    if (threadIdx.x == 0 && out_size > T_TOK * CDIM) {
        float l = 0.0f;
#pragma unroll
        for (int e = 0; e < EDIM; e++) {
            float m = g_gate_sums[e] / (float)T_TOK;
            l += m * logf(m + 1e-8f);
        }
        out[T_TOK * CDIM] = l;
    }
}

// ---------------------------------------------------------------------------
extern "C" void kernel_launch(void* const* d_in, const int* in_sizes, int n_in,
                              void* d_out, int out_size) {
    const float* x      = (const float*)d_in[0];
    const float* gumbel = (const float*)d_in[1];
    const float* gate_w = (const float*)d_in[2];
    const float* gate_b = (const float*)d_in[3];
    const float* w1     = (const float*)d_in[4];
    const float* b1     = (const float*)d_in[5];
    const float* w2     = (const float*)d_in[6];
    const float* b2     = (const float*)d_in[7];
    float* out = (float*)d_out;

    static bool attr_done = false;
    if (!attr_done) {
        cudaFuncSetAttribute(gemm_hmma<true, 16>,
                             cudaFuncAttributeMaxDynamicSharedMemorySize, GEMM_SMEM);
        cudaFuncSetAttribute(gemm_hmma<false, 64>,
                             cudaFuncAttributeMaxDynamicSharedMemorySize, GEMM_SMEM);
        attr_done = true;
    }

    init_kernel<<<1, 32>>>();
    gate_kernel<<<T_TOK, 128>>>(x, gumbel, gate_w, gate_b);
    convert_x_kernel<<<dim3(T_TOK, EDIM), 256>>>(x);
    convert_w_kernel<<<dim3(HDIM / 32, CDIM / 64, EDIM), 256>>>(w1, CDIM, HDIM, 0);
    convert_w_kernel<<<dim3(CDIM / 32, HDIM / 64, EDIM), 256>>>(w2, HDIM, CDIM, 1);
    gemm_hmma<true, 16><<<dim3(HDIM / 128, T_TOK / 128, EDIM), 128, GEMM_SMEM>>>(b1);
    gemm_hmma<false, 64><<<dim3(CDIM / 128, T_TOK / 128, EDIM), 128, GEMM_SMEM>>>(b2);
    combine_kernel<<<T_TOK, 256>>>(out);
    loss_kernel<<<1, 32>>>(out, out_size);
}

// round 11
// speedup vs baseline: 1.2616x; 1.0071x over previous
#include <cuda_runtime.h>
#include <cuda_fp16.h>
#include <math.h>
#include <stdint.h>

#define T_TOK 4096
#define CDIM  1024
#define HDIM  4096
#define EDIM  8

// ---------------- device scratch (allocation-free) ----------------
__device__ float  g_gate_sums[EDIM];
__device__ int    g_cnt[EDIM];
__device__ int    g_bucket_tok[EDIM * T_TOK];
__device__ float  g_slot_gate[EDIM * T_TOK];
__device__ __half g_Ah [(size_t)EDIM * T_TOK * CDIM];   // gathered x, fp16
__device__ __half g_Hh [(size_t)EDIM * T_TOK * HDIM];   // gelu(h), fp16
__device__ __half g_W1t[(size_t)EDIM * HDIM  * CDIM];   // w1^T fp16 [E][H][C]
__device__ __half g_W2t[(size_t)EDIM * CDIM  * HDIM];   // w2^T fp16 [E][C][H]

// ---------------- helpers ----------------
__device__ __forceinline__ uint32_t smem_u32(const void* p) {
    uint32_t a;
    asm("{ .reg .u64 t; cvta.to.shared.u64 t, %1; cvt.u32.u64 %0, t; }" : "=r"(a) : "l"(p));
    return a;
}
__device__ __forceinline__ void cp_async16(uint32_t dst, const void* src) {
    asm volatile("cp.async.cg.shared.global [%0], [%1], 16;\n" :: "r"(dst), "l"(src));
}
#define CP_COMMIT() asm volatile("cp.async.commit_group;" ::: "memory")
#define CP_WAIT1()  asm volatile("cp.async.wait_group 1;" ::: "memory")

__device__ __forceinline__ void ldmx4(uint32_t& r0, uint32_t& r1, uint32_t& r2, uint32_t& r3,
                                      uint32_t addr) {
    asm volatile("ldmatrix.sync.aligned.m8n8.x4.shared.b16 {%0,%1,%2,%3}, [%4];"
                 : "=r"(r0), "=r"(r1), "=r"(r2), "=r"(r3) : "r"(addr));
}
__device__ __forceinline__ void mma16816(float* d, const uint32_t* a, uint32_t b0, uint32_t b1) {
    asm volatile("mma.sync.aligned.m16n8k16.row.col.f32.f16.f16.f32 "
                 "{%0,%1,%2,%3}, {%4,%5,%6,%7}, {%8,%9}, {%0,%1,%2,%3};"
                 : "+f"(d[0]), "+f"(d[1]), "+f"(d[2]), "+f"(d[3])
                 : "r"(a[0]), "r"(a[1]), "r"(a[2]), "r"(a[3]), "r"(b0), "r"(b1));
}
__device__ __forceinline__ void red_add_v2(float* ptr, float a, float b) {
    asm volatile("red.global.add.v2.f32 [%0], {%1, %2};"
                 :: "l"(ptr), "f"(a), "f"(b) : "memory");
}
// byte offset in a [rows][64 halves] (128B-row) tile; full SW128 8-phase swizzle
__device__ __forceinline__ uint32_t sma64(int r, int c) {
    return (uint32_t)(((r << 3) | (c ^ (r & 7))) << 4);
}

// ---------------------------------------------------------------------------
__global__ void init_kernel() {
    int i = threadIdx.x;
    if (i < EDIM) { g_gate_sums[i] = 0.0f; g_cnt[i] = 0; }
}

__global__ void zero_out_kernel(float* __restrict__ out) {
    size_t i = (size_t)blockIdx.x * blockDim.x + threadIdx.x;
    ((float4*)out)[i] = make_float4(0.f, 0.f, 0.f, 0.f);
}

__global__ void gate_kernel(const float* __restrict__ x,
                            const float* __restrict__ gumbel,
                            const float* __restrict__ gw,
                            const float* __restrict__ gb) {
    const int t = blockIdx.x, tid = threadIdx.x;
    float acc[EDIM];
#pragma unroll
    for (int e = 0; e < EDIM; e++) acc[e] = 0.0f;
    const float* xr = x + (size_t)t * CDIM;
    for (int i = tid; i < CDIM; i += 128) {
        float xv = xr[i];
#pragma unroll
        for (int e = 0; e < EDIM; e++) acc[e] += xv * gw[i * EDIM + e];
    }
    __shared__ float red[128][EDIM];
#pragma unroll
    for (int e = 0; e < EDIM; e++) red[tid][e] = acc[e];
    __syncthreads();
    for (int s = 64; s > 0; s >>= 1) {
        if (tid < s) {
#pragma unroll
            for (int e = 0; e < EDIM; e++) red[tid][e] += red[tid + s][e];
        }
        __syncthreads();
    }
    if (tid == 0) {
        float l[EDIM]; float mx = -1e30f;
#pragma unroll
        for (int e = 0; e < EDIM; e++) {
            l[e] = red[0][e] + gb[e] + gumbel[t * EDIM + e];
            mx = fmaxf(mx, l[e]);
        }
        float sum = 0.0f;
#pragma unroll
        for (int e = 0; e < EDIM; e++) { l[e] = expf(l[e] - mx); sum += l[e]; }
        float inv = 1.0f / sum;
        float g[EDIM];
#pragma unroll
        for (int e = 0; e < EDIM; e++) { g[e] = l[e] * inv; atomicAdd(&g_gate_sums[e], g[e]); }
        int i0 = 0;
#pragma unroll
        for (int e = 1; e < EDIM; e++) if (g[e] > g[i0]) i0 = e;
        int i1 = (i0 == 0) ? 1 : 0;
#pragma unroll
        for (int e = 0; e < EDIM; e++) if (e != i0 && g[e] > g[i1]) i1 = e;
        int p0 = atomicAdd(&g_cnt[i0], 1);
        g_bucket_tok[i0 * T_TOK + p0] = t;
        g_slot_gate[i0 * T_TOK + p0] = g[i0];
        int p1 = atomicAdd(&g_cnt[i1], 1);
        g_bucket_tok[i1 * T_TOK + p1] = t;
        g_slot_gate[i1 * T_TOK + p1] = g[i1];
    }
}

// gather x rows per expert slot -> fp16 (zero-pad to 128-row boundary)
__global__ void convert_x_kernel(const float* __restrict__ x) {
    const int e = blockIdx.y, s = blockIdx.x;
    const int cnt = g_cnt[e];
    const int padded = (cnt + 127) & ~127;
    if (s >= padded) return;
    __half* dst = g_Ah + (size_t)(e * T_TOK + s) * CDIM;
    const int t = threadIdx.x;  // 256 threads x 4 floats
    if (s < cnt) {
        int tok = g_bucket_tok[e * T_TOK + s];
        float4 v = ((const float4*)(x + (size_t)tok * CDIM))[t];
        ((__half2*)dst)[2 * t + 0] = __floats2half2_rn(v.x, v.y);
        ((__half2*)dst)[2 * t + 1] = __floats2half2_rn(v.z, v.w);
    } else {
        __half2 z = __floats2half2_rn(0.f, 0.f);
        ((__half2*)dst)[2 * t + 0] = z;
        ((__half2*)dst)[2 * t + 1] = z;
    }
}

// transpose + fp16 convert: in [E][A][Bd] fp32 -> out [E][Bd][A] fp16
__global__ void convert_w_kernel(const float* __restrict__ W, int A, int Bd, int which) {
    __shared__ float s[64][33];
    const int e = blockIdx.z;
    const int a0 = blockIdx.y * 64, b0 = blockIdx.x * 32;
    const int t = threadIdx.x;  // 256
    const float* Wp = W + (size_t)e * A * Bd;
    __half* Wt = (which ? g_W2t : g_W1t) + (size_t)e * A * Bd;
    {
        const int col = t & 31;
        const int r0 = t >> 5;          // 0..7
#pragma unroll
        for (int i = 0; i < 8; i++) {
            int r = r0 + i * 8;
            s[r][col] = Wp[(size_t)(a0 + r) * Bd + b0 + col];
        }
    }
    __syncthreads();
    {
        const int col2 = t & 31;
        const int bb0  = t >> 5;
#pragma unroll
        for (int j = 0; j < 4; j++) {
            int b = bb0 + j * 8;
            __half2 hv = __floats2half2_rn(s[2 * col2][b], s[2 * col2 + 1][b]);
            *(__half2*)(Wt + (size_t)(b0 + b) * A + a0 + 2 * col2) = hv;
        }
    }
}

// ---------------------------------------------------------------------------
// HMMA grouped GEMM: BM=128, BN=128, BK=64, 128 threads (4 warps, 64x64 tiles).
// GELU=true: epilogue +b1, exact GELU -> g_Hh.
// GELU=false: epilogue +b2, scale by gate, red.global.add into out[token].
#define GEMM_SMEM (3 * 32768)
template<bool GELU, int NK>   // NK = K/64
__global__ __launch_bounds__(128, 2) void gemm_hmma(const float* __restrict__ bias,
                                                    float* __restrict__ out) {
    const int e = blockIdx.z;
    const int cnt = g_cnt[e];
    const int m0 = blockIdx.y * 128;
    if (m0 >= cnt) return;
    const int n0 = blockIdx.x * 128;

    const int K    = GELU ? CDIM : HDIM;   // row stride (halves) for A and B
    const int NTOT = GELU ? HDIM : CDIM;
    const __half* __restrict__ abase = GELU ? g_Ah  : g_Hh;
    const __half* __restrict__ bbase = GELU ? g_W1t : g_W2t;

    extern __shared__ __align__(16) char smraw[];
    const uint32_t sb = smem_u32(smraw);
    // per stage: A 128x64 halves (16384B) then B 128x64 (16384B) => 32KB/stage

    const int tid  = threadIdx.x;
    const int lane = tid & 31;
    const int w    = tid >> 5;
    const int wm   = w & 1;        // m-half of 64
    const int wn   = w >> 1;       // n-half of 64

    const __half* A0 = abase + (size_t)(e * T_TOK + m0) * K;
    const __half* B0 = bbase + ((size_t)e * NTOT + n0) * K;

    float acc[4][8][4];
#pragma unroll
    for (int i = 0; i < 4; i++)
#pragma unroll
        for (int j = 0; j < 8; j++)
#pragma unroll
            for (int q = 0; q < 4; q++) acc[i][j][q] = 0.0f;

    auto load_stage = [&](int kc) {
        const int st = kc % 3;
        const __half* ap = A0 + kc * 64;
        const __half* bp = B0 + kc * 64;
        const uint32_t aS = sb + st * 32768;
        const uint32_t bS = aS + 16384;
#pragma unroll
        for (int h = 0; h < 8; h++) {   // A: 1024 16B chunks over 128 threads
            int id = tid + h * 128;
            int row = id >> 3, c = id & 7;
            cp_async16(aS + sma64(row, c), ap + (size_t)row * K + c * 8);
        }
#pragma unroll
        for (int h = 0; h < 8; h++) {   // B: 1024 chunks
            int id = tid + h * 128;
            int row = id >> 3, c = id & 7;
            cp_async16(bS + sma64(row, c), bp + (size_t)row * K + c * 8);
        }
    };

    load_stage(0); CP_COMMIT();
    load_stage(1); CP_COMMIT();

#pragma unroll 1
    for (int kc = 0; kc < NK; kc++) {
        const int s = kc % 3;
        CP_WAIT1();
        __syncthreads();
        if (kc + 2 < NK) load_stage(kc + 2);
        CP_COMMIT();

        const uint32_t aS = sb + s * 32768;
        const uint32_t bS = aS + 16384;
#pragma unroll
        for (int ks = 0; ks < 4; ks++) {
            uint32_t afr[4][4];
#pragma unroll
            for (int mi = 0; mi < 4; mi++) {
                int row = wm * 64 + mi * 16 + ((lane >> 3) & 1) * 8 + (lane & 7);
                int ch  = ks * 2 + (lane >> 4);
                ldmx4(afr[mi][0], afr[mi][1], afr[mi][2], afr[mi][3], aS + sma64(row, ch));
            }
            uint32_t bfr[4][4];
#pragma unroll
            for (int nj = 0; nj < 4; nj++) {
                int row = wn * 64 + nj * 16 + (lane >> 4) * 8 + (lane & 7);
                int ch  = ks * 2 + ((lane >> 3) & 1);
                ldmx4(bfr[nj][0], bfr[nj][1], bfr[nj][2], bfr[nj][3], bS + sma64(row, ch));
            }
#pragma unroll
            for (int mi = 0; mi < 4; mi++)
#pragma unroll
                for (int nj = 0; nj < 4; nj++) {
                    mma16816(acc[mi][nj * 2 + 0], afr[mi], bfr[nj][0], bfr[nj][1]);
                    mma16816(acc[mi][nj * 2 + 1], afr[mi], bfr[nj][2], bfr[nj][3]);
                }
        }
        __syncthreads();
    }

    // ---- epilogue ----
    const int r0l = lane >> 2;
    const int c0l = (lane & 3) * 2;
#pragma unroll
    for (int mi = 0; mi < 4; mi++) {
        // per-row token/gate lookups (GEMM2 only)
        int   tok[2];
        float gt[2];
#pragma unroll
        for (int hh = 0; hh < 2; hh++) {
            int lrow = m0 + wm * 64 + mi * 16 + r0l + hh * 8;
            if (!GELU && lrow < cnt) {
                tok[hh] = g_bucket_tok[e * T_TOK + lrow];
                gt[hh]  = g_slot_gate[e * T_TOK + lrow];
            } else {
                tok[hh] = 0; gt[hh] = 0.f;
            }
        }
#pragma unroll
        for (int ni = 0; ni < 8; ni++) {
            int gc = n0 + wn * 64 + ni * 8 + c0l;
            float bv0 = __ldg(&bias[(size_t)e * NTOT + gc]);
            float bv1 = __ldg(&bias[(size_t)e * NTOT + gc + 1]);
#pragma unroll
            for (int hh = 0; hh < 2; hh++) {
                int lrow = m0 + wm * 64 + mi * 16 + r0l + hh * 8;
                float v0 = acc[mi][ni][hh * 2 + 0] + bv0;
                float v1 = acc[mi][ni][hh * 2 + 1] + bv1;
                if (GELU) {
                    size_t slot = (size_t)(e * T_TOK) + lrow;
                    float q0 = 0.5f * v0 * (1.0f + erff(v0 * 0.70710678118654752f));
                    float q1 = 0.5f * v1 * (1.0f + erff(v1 * 0.70710678118654752f));
                    *(__half2*)(g_Hh + slot * HDIM + gc) = __floats2half2_rn(q0, q1);
                } else if (lrow < cnt) {
                    red_add_v2(out + (size_t)tok[hh] * CDIM + gc, gt[hh] * v0, gt[hh] * v1);
                }
            }
        }
    }
}

// ---------------------------------------------------------------------------
__global__ void loss_kernel(float* __restrict__ out, int out_size) {
    if (threadIdx.x == 0 && out_size > T_TOK * CDIM) {
        float l = 0.0f;
#pragma unroll
        for (int e = 0; e < EDIM; e++) {
            float m = g_gate_sums[e] / (float)T_TOK;
            l += m * logf(m + 1e-8f);
        }
        out[T_TOK * CDIM] = l;
    }
}

// ---------------------------------------------------------------------------
extern "C" void kernel_launch(void* const* d_in, const int* in_sizes, int n_in,
                              void* d_out, int out_size) {
    const float* x      = (const float*)d_in[0];
    const float* gumbel = (const float*)d_in[1];
    const float* gate_w = (const float*)d_in[2];
    const float* gate_b = (const float*)d_in[3];
    const float* w1     = (const float*)d_in[4];
    const float* b1     = (const float*)d_in[5];
    const float* w2     = (const float*)d_in[6];
    const float* b2     = (const float*)d_in[7];
    float* out = (float*)d_out;

    static bool attr_done = false;
    if (!attr_done) {
        cudaFuncSetAttribute(gemm_hmma<true, 16>,
                             cudaFuncAttributeMaxDynamicSharedMemorySize, GEMM_SMEM);
        cudaFuncSetAttribute(gemm_hmma<false, 64>,
                             cudaFuncAttributeMaxDynamicSharedMemorySize, GEMM_SMEM);
        attr_done = true;
    }

    init_kernel<<<1, 32>>>();
    zero_out_kernel<<<T_TOK, 256>>>(out);   // T_TOK*256*4 = T_TOK*CDIM floats
    gate_kernel<<<T_TOK, 128>>>(x, gumbel, gate_w, gate_b);
    convert_x_kernel<<<dim3(T_TOK, EDIM), 256>>>(x);
    convert_w_kernel<<<dim3(HDIM / 32, CDIM / 64, EDIM), 256>>>(w1, CDIM, HDIM, 0);
    convert_w_kernel<<<dim3(CDIM / 32, HDIM / 64, EDIM), 256>>>(w2, HDIM, CDIM, 1);
    gemm_hmma<true, 16><<<dim3(HDIM / 128, T_TOK / 128, EDIM), 128, GEMM_SMEM>>>(b1, out);
    gemm_hmma<false, 64><<<dim3(CDIM / 128, T_TOK / 128, EDIM), 128, GEMM_SMEM>>>(b2, out);
    loss_kernel<<<1, 32>>>(out, out_size);
}

// round 12
// speedup vs baseline: 1.3071x; 1.0361x over previous
#include <cuda_runtime.h>
#include <cuda_fp16.h>
#include <math.h>
#include <stdint.h>

#define T_TOK 4096
#define CDIM  1024
#define HDIM  4096
#define EDIM  8

// ---------------- device scratch (allocation-free) ----------------
__device__ float  g_gate_sums[EDIM];
__device__ int    g_cnt[EDIM];
__device__ int    g_bucket_tok[EDIM * T_TOK];
__device__ float  g_slot_gate[EDIM * T_TOK];
__device__ __half g_Ah [(size_t)EDIM * T_TOK * CDIM];   // gathered x, fp16
__device__ __half g_Hh [(size_t)EDIM * T_TOK * HDIM];   // gelu(h), fp16
__device__ __half g_W1t[(size_t)EDIM * HDIM  * CDIM];   // w1^T fp16 [E][H][C]
__device__ __half g_W2t[(size_t)EDIM * CDIM  * HDIM];   // w2^T fp16 [E][C][H]

// ---------------- helpers ----------------
__device__ __forceinline__ uint32_t smem_u32(const void* p) {
    uint32_t a;
    asm("{ .reg .u64 t; cvta.to.shared.u64 t, %1; cvt.u32.u64 %0, t; }" : "=r"(a) : "l"(p));
    return a;
}
__device__ __forceinline__ void cp_async16(uint32_t dst, const void* src) {
    asm volatile("cp.async.cg.shared.global [%0], [%1], 16;\n" :: "r"(dst), "l"(src));
}
#define CP_COMMIT() asm volatile("cp.async.commit_group;" ::: "memory")
#define CP_WAIT1()  asm volatile("cp.async.wait_group 1;" ::: "memory")

__device__ __forceinline__ void ldmx4(uint32_t& r0, uint32_t& r1, uint32_t& r2, uint32_t& r3,
                                      uint32_t addr) {
    asm volatile("ldmatrix.sync.aligned.m8n8.x4.shared.b16 {%0,%1,%2,%3}, [%4];"
                 : "=r"(r0), "=r"(r1), "=r"(r2), "=r"(r3) : "r"(addr));
}
__device__ __forceinline__ void mma16816(float* d, const uint32_t* a, uint32_t b0, uint32_t b1) {
    asm volatile("mma.sync.aligned.m16n8k16.row.col.f32.f16.f16.f32 "
                 "{%0,%1,%2,%3}, {%4,%5,%6,%7}, {%8,%9}, {%0,%1,%2,%3};"
                 : "+f"(d[0]), "+f"(d[1]), "+f"(d[2]), "+f"(d[3])
                 : "r"(a[0]), "r"(a[1]), "r"(a[2]), "r"(a[3]), "r"(b0), "r"(b1));
}
__device__ __forceinline__ void red_add_v2(float* ptr, float a, float b) {
    asm volatile("red.global.add.v2.f32 [%0], {%1, %2};"
                 :: "l"(ptr), "f"(a), "f"(b) : "memory");
}
// byte offset in a [rows][64 halves] (128B-row) tile; full SW128 8-phase swizzle
__device__ __forceinline__ uint32_t sma64(int r, int c) {
    return (uint32_t)(((r << 3) | (c ^ (r & 7))) << 4);
}

// ---------------------------------------------------------------------------
__global__ void init_kernel() {
    int i = threadIdx.x;
    if (i < EDIM) { g_gate_sums[i] = 0.0f; g_cnt[i] = 0; }
}

__global__ void zero_out_kernel(float* __restrict__ out) {
    size_t i = (size_t)blockIdx.x * blockDim.x + threadIdx.x;
    ((float4*)out)[i] = make_float4(0.f, 0.f, 0.f, 0.f);
}

// One warp per token: logits via shuffle reduction, gumbel softmax, top-2,
// bucketing, AND direct fp16 scatter of the x row into both expert slots.
__global__ __launch_bounds__(256) void gate_kernel(const float* __restrict__ x,
                                                   const float* __restrict__ gumbel,
                                                   const float* __restrict__ gw,
                                                   const float* __restrict__ gb) {
    const int warp = threadIdx.x >> 5, lane = threadIdx.x & 31;
    const int t = blockIdx.x * 8 + warp;
    const float* xr = x + (size_t)t * CDIM;

    float2 xv[16];
    float acc[EDIM];
#pragma unroll
    for (int e = 0; e < EDIM; e++) acc[e] = 0.0f;
#pragma unroll
    for (int i = 0; i < 16; i++) {
        int col = i * 64 + lane * 2;
        xv[i] = *(const float2*)(xr + col);
        float4 w0 = *(const float4*)(gw + (size_t)col * 8);
        float4 w1v = *(const float4*)(gw + (size_t)col * 8 + 4);
        float4 w2v = *(const float4*)(gw + (size_t)col * 8 + 8);
        float4 w3v = *(const float4*)(gw + (size_t)col * 8 + 12);
        acc[0] += xv[i].x * w0.x + xv[i].y * w2v.x;
        acc[1] += xv[i].x * w0.y + xv[i].y * w2v.y;
        acc[2] += xv[i].x * w0.z + xv[i].y * w2v.z;
        acc[3] += xv[i].x * w0.w + xv[i].y * w2v.w;
        acc[4] += xv[i].x * w1v.x + xv[i].y * w3v.x;
        acc[5] += xv[i].x * w1v.y + xv[i].y * w3v.y;
        acc[6] += xv[i].x * w1v.z + xv[i].y * w3v.z;
        acc[7] += xv[i].x * w1v.w + xv[i].y * w3v.w;
    }
#pragma unroll
    for (int off = 16; off; off >>= 1) {
#pragma unroll
        for (int e = 0; e < EDIM; e++)
            acc[e] += __shfl_xor_sync(0xffffffffu, acc[e], off);
    }

    // all lanes hold identical sums; compute gates redundantly
    float l[EDIM]; float mx = -1e30f;
#pragma unroll
    for (int e = 0; e < EDIM; e++) {
        l[e] = acc[e] + gb[e] + gumbel[t * EDIM + e];
        mx = fmaxf(mx, l[e]);
    }
    float sum = 0.0f;
#pragma unroll
    for (int e = 0; e < EDIM; e++) { l[e] = expf(l[e] - mx); sum += l[e]; }
    float inv = 1.0f / sum;
    float g[EDIM];
#pragma unroll
    for (int e = 0; e < EDIM; e++) g[e] = l[e] * inv;
    int i0 = 0;
#pragma unroll
    for (int e = 1; e < EDIM; e++) if (g[e] > g[i0]) i0 = e;
    int i1 = (i0 == 0) ? 1 : 0;
#pragma unroll
    for (int e = 0; e < EDIM; e++) if (e != i0 && g[e] > g[i1]) i1 = e;

    int p0 = 0, p1 = 0;
    if (lane == 0) {
#pragma unroll
        for (int e = 0; e < EDIM; e++) atomicAdd(&g_gate_sums[e], g[e]);
        p0 = atomicAdd(&g_cnt[i0], 1);
        g_bucket_tok[i0 * T_TOK + p0] = t;
        g_slot_gate[i0 * T_TOK + p0] = g[i0];
        p1 = atomicAdd(&g_cnt[i1], 1);
        g_bucket_tok[i1 * T_TOK + p1] = t;
        g_slot_gate[i1 * T_TOK + p1] = g[i1];
    }
    p0 = __shfl_sync(0xffffffffu, p0, 0);
    p1 = __shfl_sync(0xffffffffu, p1, 0);

    // scatter fp16 x row into both expert slots
    __half* d0 = g_Ah + (size_t)(i0 * T_TOK + p0) * CDIM;
    __half* d1 = g_Ah + (size_t)(i1 * T_TOK + p1) * CDIM;
#pragma unroll
    for (int i = 0; i < 16; i++) {
        int col = i * 64 + lane * 2;
        __half2 h = __floats2half2_rn(xv[i].x, xv[i].y);
        *(__half2*)(d0 + col) = h;
        *(__half2*)(d1 + col) = h;
    }
}

// transpose + fp16 convert: in [E][A][Bd] fp32 -> out [E][Bd][A] fp16
__global__ void convert_w_kernel(const float* __restrict__ W, int A, int Bd, int which) {
    __shared__ float s[64][33];
    const int e = blockIdx.z;
    const int a0 = blockIdx.y * 64, b0 = blockIdx.x * 32;
    const int t = threadIdx.x;  // 256
    const float* Wp = W + (size_t)e * A * Bd;
    __half* Wt = (which ? g_W2t : g_W1t) + (size_t)e * A * Bd;
    {
        const int col = t & 31;
        const int r0 = t >> 5;          // 0..7
#pragma unroll
        for (int i = 0; i < 8; i++) {
            int r = r0 + i * 8;
            s[r][col] = Wp[(size_t)(a0 + r) * Bd + b0 + col];
        }
    }
    __syncthreads();
    {
        const int col2 = t & 31;
        const int bb0  = t >> 5;
#pragma unroll
        for (int j = 0; j < 4; j++) {
            int b = bb0 + j * 8;
            __half2 hv = __floats2half2_rn(s[2 * col2][b], s[2 * col2 + 1][b]);
            *(__half2*)(Wt + (size_t)(b0 + b) * A + a0 + 2 * col2) = hv;
        }
    }
}

// ---------------------------------------------------------------------------
// HMMA grouped GEMM: BM=128, BN=128, BK=64, 128 threads (4 warps, 64x64 tiles).
// GELU=true: epilogue +b1, exact GELU -> g_Hh.
// GELU=false: epilogue +b2, scale by gate, red.global.add into out[token].
#define GEMM_SMEM (3 * 32768)
template<bool GELU, int NK>   // NK = K/64
__global__ __launch_bounds__(128, 2) void gemm_hmma(const float* __restrict__ bias,
                                                    float* __restrict__ out) {
    const int e = blockIdx.z;
    const int cnt = g_cnt[e];
    const int m0 = blockIdx.y * 128;
    if (m0 >= cnt) return;
    const int n0 = blockIdx.x * 128;

    const int K    = GELU ? CDIM : HDIM;   // row stride (halves) for A and B
    const int NTOT = GELU ? HDIM : CDIM;
    const __half* __restrict__ abase = GELU ? g_Ah  : g_Hh;
    const __half* __restrict__ bbase = GELU ? g_W1t : g_W2t;

    extern __shared__ __align__(16) char smraw[];
    const uint32_t sb = smem_u32(smraw);

    const int tid  = threadIdx.x;
    const int lane = tid & 31;
    const int w    = tid >> 5;
    const int wm   = w & 1;        // m-half of 64
    const int wn   = w >> 1;       // n-half of 64

    const __half* A0 = abase + (size_t)(e * T_TOK + m0) * K;
    const __half* B0 = bbase + ((size_t)e * NTOT + n0) * K;

    float acc[4][8][4];
#pragma unroll
    for (int i = 0; i < 4; i++)
#pragma unroll
        for (int j = 0; j < 8; j++)
#pragma unroll
            for (int q = 0; q < 4; q++) acc[i][j][q] = 0.0f;

    auto load_stage = [&](int kc) {
        const int st = kc % 3;
        const __half* ap = A0 + kc * 64;
        const __half* bp = B0 + kc * 64;
        const uint32_t aS = sb + st * 32768;
        const uint32_t bS = aS + 16384;
#pragma unroll
        for (int h = 0; h < 8; h++) {   // A: 1024 16B chunks over 128 threads
            int id = tid + h * 128;
            int row = id >> 3, c = id & 7;
            cp_async16(aS + sma64(row, c), ap + (size_t)row * K + c * 8);
        }
#pragma unroll
        for (int h = 0; h < 8; h++) {   // B: 1024 chunks
            int id = tid + h * 128;
            int row = id >> 3, c = id & 7;
            cp_async16(bS + sma64(row, c), bp + (size_t)row * K + c * 8);
        }
    };

    load_stage(0); CP_COMMIT();
    load_stage(1); CP_COMMIT();

#pragma unroll 1
    for (int kc = 0; kc < NK; kc++) {
        const int s = kc % 3;
        CP_WAIT1();
        __syncthreads();
        if (kc + 2 < NK) load_stage(kc + 2);
        CP_COMMIT();

        const uint32_t aS = sb + s * 32768;
        const uint32_t bS = aS + 16384;
#pragma unroll
        for (int ks = 0; ks < 4; ks++) {
            uint32_t afr[4][4];
#pragma unroll
            for (int mi = 0; mi < 4; mi++) {
                int row = wm * 64 + mi * 16 + ((lane >> 3) & 1) * 8 + (lane & 7);
                int ch  = ks * 2 + (lane >> 4);
                ldmx4(afr[mi][0], afr[mi][1], afr[mi][2], afr[mi][3], aS + sma64(row, ch));
            }
            uint32_t bfr[4][4];
#pragma unroll
            for (int nj = 0; nj < 4; nj++) {
                int row = wn * 64 + nj * 16 + (lane >> 4) * 8 + (lane & 7);
                int ch  = ks * 2 + ((lane >> 3) & 1);
                ldmx4(bfr[nj][0], bfr[nj][1], bfr[nj][2], bfr[nj][3], bS + sma64(row, ch));
            }
#pragma unroll
            for (int mi = 0; mi < 4; mi++)
#pragma unroll
                for (int nj = 0; nj < 4; nj++) {
                    mma16816(acc[mi][nj * 2 + 0], afr[mi], bfr[nj][0], bfr[nj][1]);
                    mma16816(acc[mi][nj * 2 + 1], afr[mi], bfr[nj][2], bfr[nj][3]);
                }
        }
        __syncthreads();
    }

    // ---- epilogue ----
    const int r0l = lane >> 2;
    const int c0l = (lane & 3) * 2;
#pragma unroll
    for (int mi = 0; mi < 4; mi++) {
        int   tok[2];
        float gt[2];
#pragma unroll
        for (int hh = 0; hh < 2; hh++) {
            int lrow = m0 + wm * 64 + mi * 16 + r0l + hh * 8;
            if (!GELU && lrow < cnt) {
                tok[hh] = g_bucket_tok[e * T_TOK + lrow];
                gt[hh]  = g_slot_gate[e * T_TOK + lrow];
            } else {
                tok[hh] = 0; gt[hh] = 0.f;
            }
        }
#pragma unroll
        for (int ni = 0; ni < 8; ni++) {
            int gc = n0 + wn * 64 + ni * 8 + c0l;
            float bv0 = __ldg(&bias[(size_t)e * NTOT + gc]);
            float bv1 = __ldg(&bias[(size_t)e * NTOT + gc + 1]);
#pragma unroll
            for (int hh = 0; hh < 2; hh++) {
                int lrow = m0 + wm * 64 + mi * 16 + r0l + hh * 8;
                float v0 = acc[mi][ni][hh * 2 + 0] + bv0;
                float v1 = acc[mi][ni][hh * 2 + 1] + bv1;
                if (GELU) {
                    size_t slot = (size_t)(e * T_TOK) + lrow;
                    float q0 = 0.5f * v0 * (1.0f + erff(v0 * 0.70710678118654752f));
                    float q1 = 0.5f * v1 * (1.0f + erff(v1 * 0.70710678118654752f));
                    *(__half2*)(g_Hh + slot * HDIM + gc) = __floats2half2_rn(q0, q1);
                } else if (lrow < cnt) {
                    red_add_v2(out + (size_t)tok[hh] * CDIM + gc, gt[hh] * v0, gt[hh] * v1);
                }
            }
        }
    }
}

// ---------------------------------------------------------------------------
__global__ void loss_kernel(float* __restrict__ out, int out_size) {
    if (threadIdx.x == 0 && out_size > T_TOK * CDIM) {
        float l = 0.0f;
#pragma unroll
        for (int e = 0; e < EDIM; e++) {
            float m = g_gate_sums[e] / (float)T_TOK;
            l += m * logf(m + 1e-8f);
        }
        out[T_TOK * CDIM] = l;
    }
}

// ---------------------------------------------------------------------------
extern "C" void kernel_launch(void* const* d_in, const int* in_sizes, int n_in,
                              void* d_out, int out_size) {
    const float* x      = (const float*)d_in[0];
    const float* gumbel = (const float*)d_in[1];
    const float* gate_w = (const float*)d_in[2];
    const float* gate_b = (const float*)d_in[3];
    const float* w1     = (const float*)d_in[4];
    const float* b1     = (const float*)d_in[5];
    const float* w2     = (const float*)d_in[6];
    const float* b2     = (const float*)d_in[7];
    float* out = (float*)d_out;

    static bool attr_done = false;
    if (!attr_done) {
        cudaFuncSetAttribute(gemm_hmma<true, 16>,
                             cudaFuncAttributeMaxDynamicSharedMemorySize, GEMM_SMEM);
        cudaFuncSetAttribute(gemm_hmma<false, 64>,
                             cudaFuncAttributeMaxDynamicSharedMemorySize, GEMM_SMEM);
        attr_done = true;
    }

    init_kernel<<<1, 32>>>();
    zero_out_kernel<<<T_TOK, 256>>>(out);
    gate_kernel<<<T_TOK / 8, 256>>>(x, gumbel, gate_w, gate_b);
    convert_w_kernel<<<dim3(HDIM / 32, CDIM / 64, EDIM), 256>>>(w1, CDIM, HDIM, 0);
    convert_w_kernel<<<dim3(CDIM / 32, HDIM / 64, EDIM), 256>>>(w2, HDIM, CDIM, 1);
    gemm_hmma<true, 16><<<dim3(HDIM / 128, T_TOK / 128, EDIM), 128, GEMM_SMEM>>>(b1, out);
    gemm_hmma<false, 64><<<dim3(CDIM / 128, T_TOK / 128, EDIM), 128, GEMM_SMEM>>>(b2, out);
    loss_kernel<<<1, 32>>>(out, out_size);
}

// round 13
// speedup vs baseline: 1.3127x; 1.0043x over previous
#include <cuda_runtime.h>
#include <cuda_fp16.h>
#include <math.h>
#include <stdint.h>

#define T_TOK 4096
#define CDIM  1024
#define HDIM  4096
#define EDIM  8

// ---------------- device scratch (allocation-free) ----------------
__device__ float  g_gate_sums[EDIM];
__device__ int    g_cnt[EDIM];
__device__ int    g_bucket_tok[EDIM * T_TOK];
__device__ float  g_slot_gate[EDIM * T_TOK];
__device__ __half g_Ah [(size_t)EDIM * T_TOK * CDIM];   // gathered x, fp16
__device__ __half g_Hh [(size_t)EDIM * T_TOK * HDIM];   // gelu(h), fp16
__device__ __half g_W1t[(size_t)EDIM * HDIM  * CDIM];   // w1^T fp16 [E][H][C]
__device__ __half g_W2t[(size_t)EDIM * CDIM  * HDIM];   // w2^T fp16 [E][C][H]

// ---------------- helpers ----------------
__device__ __forceinline__ uint32_t smem_u32(const void* p) {
    uint32_t a;
    asm("{ .reg .u64 t; cvta.to.shared.u64 t, %1; cvt.u32.u64 %0, t; }" : "=r"(a) : "l"(p));
    return a;
}
__device__ __forceinline__ void cp_async16(uint32_t dst, const void* src) {
    asm volatile("cp.async.cg.shared.global [%0], [%1], 16;\n" :: "r"(dst), "l"(src));
}
#define CP_COMMIT() asm volatile("cp.async.commit_group;" ::: "memory")
#define CP_WAIT1()  asm volatile("cp.async.wait_group 1;" ::: "memory")

__device__ __forceinline__ void ldmx4(uint32_t& r0, uint32_t& r1, uint32_t& r2, uint32_t& r3,
                                      uint32_t addr) {
    asm volatile("ldmatrix.sync.aligned.m8n8.x4.shared.b16 {%0,%1,%2,%3}, [%4];"
                 : "=r"(r0), "=r"(r1), "=r"(r2), "=r"(r3) : "r"(addr));
}
__device__ __forceinline__ void mma16816(float* d, const uint32_t* a, uint32_t b0, uint32_t b1) {
    asm volatile("mma.sync.aligned.m16n8k16.row.col.f32.f16.f16.f32 "
                 "{%0,%1,%2,%3}, {%4,%5,%6,%7}, {%8,%9}, {%0,%1,%2,%3};"
                 : "+f"(d[0]), "+f"(d[1]), "+f"(d[2]), "+f"(d[3])
                 : "r"(a[0]), "r"(a[1]), "r"(a[2]), "r"(a[3]), "r"(b0), "r"(b1));
}
__device__ __forceinline__ void red_add_v2(float* ptr, float a, float b) {
    asm volatile("red.global.add.v2.f32 [%0], {%1, %2};"
                 :: "l"(ptr), "f"(a), "f"(b) : "memory");
}
// byte offset in a [rows][64 halves] (128B-row) tile; full SW128 8-phase swizzle
__device__ __forceinline__ uint32_t sma64(int r, int c) {
    return (uint32_t)(((r << 3) | (c ^ (r & 7))) << 4);
}

// ---------------------------------------------------------------------------
// zero out + init counters (block 0 thread 0..EDIM does counters)
__global__ void zero_out_kernel(float* __restrict__ out) {
    size_t i = (size_t)blockIdx.x * blockDim.x + threadIdx.x;
    ((float4*)out)[i] = make_float4(0.f, 0.f, 0.f, 0.f);
    if (blockIdx.x == 0 && threadIdx.x < EDIM) {
        g_gate_sums[threadIdx.x] = 0.0f;
        g_cnt[threadIdx.x] = 0;
    }
}

// One warp per token: logits via shuffle reduction, gumbel softmax, top-2,
// bucketing, AND direct fp16 scatter of the x row into both expert slots.
__global__ __launch_bounds__(256) void gate_kernel(const float* __restrict__ x,
                                                   const float* __restrict__ gumbel,
                                                   const float* __restrict__ gw,
                                                   const float* __restrict__ gb) {
    const int warp = threadIdx.x >> 5, lane = threadIdx.x & 31;
    const int t = blockIdx.x * 8 + warp;
    const float* xr = x + (size_t)t * CDIM;

    float2 xv[16];
    float acc[EDIM];
#pragma unroll
    for (int e = 0; e < EDIM; e++) acc[e] = 0.0f;
#pragma unroll
    for (int i = 0; i < 16; i++) {
        int col = i * 64 + lane * 2;
        xv[i] = *(const float2*)(xr + col);
        float4 w0 = *(const float4*)(gw + (size_t)col * 8);
        float4 w1v = *(const float4*)(gw + (size_t)col * 8 + 4);
        float4 w2v = *(const float4*)(gw + (size_t)col * 8 + 8);
        float4 w3v = *(const float4*)(gw + (size_t)col * 8 + 12);
        acc[0] += xv[i].x * w0.x + xv[i].y * w2v.x;
        acc[1] += xv[i].x * w0.y + xv[i].y * w2v.y;
        acc[2] += xv[i].x * w0.z + xv[i].y * w2v.z;
        acc[3] += xv[i].x * w0.w + xv[i].y * w2v.w;
        acc[4] += xv[i].x * w1v.x + xv[i].y * w3v.x;
        acc[5] += xv[i].x * w1v.y + xv[i].y * w3v.y;
        acc[6] += xv[i].x * w1v.z + xv[i].y * w3v.z;
        acc[7] += xv[i].x * w1v.w + xv[i].y * w3v.w;
    }
#pragma unroll
    for (int off = 16; off; off >>= 1) {
#pragma unroll
        for (int e = 0; e < EDIM; e++)
            acc[e] += __shfl_xor_sync(0xffffffffu, acc[e], off);
    }

    float l[EDIM]; float mx = -1e30f;
#pragma unroll
    for (int e = 0; e < EDIM; e++) {
        l[e] = acc[e] + gb[e] + gumbel[t * EDIM + e];
        mx = fmaxf(mx, l[e]);
    }
    float sum = 0.0f;
#pragma unroll
    for (int e = 0; e < EDIM; e++) { l[e] = expf(l[e] - mx); sum += l[e]; }
    float inv = 1.0f / sum;
    float g[EDIM];
#pragma unroll
    for (int e = 0; e < EDIM; e++) g[e] = l[e] * inv;
    int i0 = 0;
#pragma unroll
    for (int e = 1; e < EDIM; e++) if (g[e] > g[i0]) i0 = e;
    int i1 = (i0 == 0) ? 1 : 0;
#pragma unroll
    for (int e = 0; e < EDIM; e++) if (e != i0 && g[e] > g[i1]) i1 = e;

    int p0 = 0, p1 = 0;
    if (lane == 0) {
#pragma unroll
        for (int e = 0; e < EDIM; e++) atomicAdd(&g_gate_sums[e], g[e]);
        p0 = atomicAdd(&g_cnt[i0], 1);
        g_bucket_tok[i0 * T_TOK + p0] = t;
        g_slot_gate[i0 * T_TOK + p0] = g[i0];
        p1 = atomicAdd(&g_cnt[i1], 1);
        g_bucket_tok[i1 * T_TOK + p1] = t;
        g_slot_gate[i1 * T_TOK + p1] = g[i1];
    }
    p0 = __shfl_sync(0xffffffffu, p0, 0);
    p1 = __shfl_sync(0xffffffffu, p1, 0);

    __half* d0 = g_Ah + (size_t)(i0 * T_TOK + p0) * CDIM;
    __half* d1 = g_Ah + (size_t)(i1 * T_TOK + p1) * CDIM;
#pragma unroll
    for (int i = 0; i < 16; i++) {
        int col = i * 64 + lane * 2;
        __half2 h = __floats2half2_rn(xv[i].x, xv[i].y);
        *(__half2*)(d0 + col) = h;
        *(__half2*)(d1 + col) = h;
    }
}

// transpose + fp16 convert: in [E][A][Bd] fp32 -> out [E][Bd][A] fp16
__global__ void convert_w_kernel(const float* __restrict__ W, int A, int Bd, int which) {
    __shared__ float s[64][33];
    const int e = blockIdx.z;
    const int a0 = blockIdx.y * 64, b0 = blockIdx.x * 32;
    const int t = threadIdx.x;  // 256
    const float* Wp = W + (size_t)e * A * Bd;
    __half* Wt = (which ? g_W2t : g_W1t) + (size_t)e * A * Bd;
    {
        const int col = t & 31;
        const int r0 = t >> 5;
#pragma unroll
        for (int i = 0; i < 8; i++) {
            int r = r0 + i * 8;
            s[r][col] = Wp[(size_t)(a0 + r) * Bd + b0 + col];
        }
    }
    __syncthreads();
    {
        const int col2 = t & 31;
        const int bb0  = t >> 5;
#pragma unroll
        for (int j = 0; j < 4; j++) {
            int b = bb0 + j * 8;
            __half2 hv = __floats2half2_rn(s[2 * col2][b], s[2 * col2 + 1][b]);
            *(__half2*)(Wt + (size_t)(b0 + b) * A + a0 + 2 * col2) = hv;
        }
    }
}

// ---------------------------------------------------------------------------
// HMMA grouped GEMM: BM=128, BN=128, BK=64, 128 threads (4 warps, 64x64 tiles).
#define GEMM_SMEM (3 * 32768)
template<bool GELU, int NK>   // NK = K/64
__global__ __launch_bounds__(128, 2) void gemm_hmma(const float* __restrict__ bias,
                                                    float* __restrict__ out) {
    const int e = blockIdx.z;
    const int cnt = g_cnt[e];
    const int m0 = blockIdx.y * 128;
    if (m0 >= cnt) return;
    const int n0 = blockIdx.x * 128;

    const int K    = GELU ? CDIM : HDIM;
    const int NTOT = GELU ? HDIM : CDIM;
    const __half* __restrict__ abase = GELU ? g_Ah  : g_Hh;
    const __half* __restrict__ bbase = GELU ? g_W1t : g_W2t;

    extern __shared__ __align__(16) char smraw[];
    const uint32_t sb = smem_u32(smraw);

    const int tid  = threadIdx.x;
    const int lane = tid & 31;
    const int w    = tid >> 5;
    const int wm   = w & 1;
    const int wn   = w >> 1;

    const __half* A0 = abase + (size_t)(e * T_TOK + m0) * K;
    const __half* B0 = bbase + ((size_t)e * NTOT + n0) * K;

    float acc[4][8][4];
#pragma unroll
    for (int i = 0; i < 4; i++)
#pragma unroll
        for (int j = 0; j < 8; j++)
#pragma unroll
            for (int q = 0; q < 4; q++) acc[i][j][q] = 0.0f;

    auto load_stage = [&](int kc) {
        const int st = kc % 3;
        const __half* ap = A0 + kc * 64;
        const __half* bp = B0 + kc * 64;
        const uint32_t aS = sb + st * 32768;
        const uint32_t bS = aS + 16384;
#pragma unroll
        for (int h = 0; h < 8; h++) {
            int id = tid + h * 128;
            int row = id >> 3, c = id & 7;
            cp_async16(aS + sma64(row, c), ap + (size_t)row * K + c * 8);
        }
#pragma unroll
        for (int h = 0; h < 8; h++) {
            int id = tid + h * 128;
            int row = id >> 3, c = id & 7;
            cp_async16(bS + sma64(row, c), bp + (size_t)row * K + c * 8);
        }
    };

    load_stage(0); CP_COMMIT();
    load_stage(1); CP_COMMIT();

#pragma unroll 1
    for (int kc = 0; kc < NK; kc++) {
        const int s = kc % 3;
        CP_WAIT1();
        __syncthreads();
        if (kc + 2 < NK) load_stage(kc + 2);
        CP_COMMIT();

        const uint32_t aS = sb + s * 32768;
        const uint32_t bS = aS + 16384;
#pragma unroll
        for (int ks = 0; ks < 4; ks++) {
            uint32_t afr[4][4];
#pragma unroll
            for (int mi = 0; mi < 4; mi++) {
                int row = wm * 64 + mi * 16 + ((lane >> 3) & 1) * 8 + (lane & 7);
                int ch  = ks * 2 + (lane >> 4);
                ldmx4(afr[mi][0], afr[mi][1], afr[mi][2], afr[mi][3], aS + sma64(row, ch));
            }
            uint32_t bfr[4][4];
#pragma unroll
            for (int nj = 0; nj < 4; nj++) {
                int row = wn * 64 + nj * 16 + (lane >> 4) * 8 + (lane & 7);
                int ch  = ks * 2 + ((lane >> 3) & 1);
                ldmx4(bfr[nj][0], bfr[nj][1], bfr[nj][2], bfr[nj][3], bS + sma64(row, ch));
            }
#pragma unroll
            for (int mi = 0; mi < 4; mi++)
#pragma unroll
                for (int nj = 0; nj < 4; nj++) {
                    mma16816(acc[mi][nj * 2 + 0], afr[mi], bfr[nj][0], bfr[nj][1]);
                    mma16816(acc[mi][nj * 2 + 1], afr[mi], bfr[nj][2], bfr[nj][3]);
                }
        }
        __syncthreads();
    }

    // ---- epilogue ----
    const int r0l = lane >> 2;
    const int c0l = (lane & 3) * 2;
#pragma unroll
    for (int mi = 0; mi < 4; mi++) {
        int   tok[2];
        float gt[2];
#pragma unroll
        for (int hh = 0; hh < 2; hh++) {
            int lrow = m0 + wm * 64 + mi * 16 + r0l + hh * 8;
            if (!GELU && lrow < cnt) {
                tok[hh] = g_bucket_tok[e * T_TOK + lrow];
                gt[hh]  = g_slot_gate[e * T_TOK + lrow];
            } else {
                tok[hh] = 0; gt[hh] = 0.f;
            }
        }
#pragma unroll
        for (int ni = 0; ni < 8; ni++) {
            int gc = n0 + wn * 64 + ni * 8 + c0l;
            float bv0 = __ldg(&bias[(size_t)e * NTOT + gc]);
            float bv1 = __ldg(&bias[(size_t)e * NTOT + gc + 1]);
#pragma unroll
            for (int hh = 0; hh < 2; hh++) {
                int lrow = m0 + wm * 64 + mi * 16 + r0l + hh * 8;
                float v0 = acc[mi][ni][hh * 2 + 0] + bv0;
                float v1 = acc[mi][ni][hh * 2 + 1] + bv1;
                if (GELU) {
                    size_t slot = (size_t)(e * T_TOK) + lrow;
                    float q0 = 0.5f * v0 * (1.0f + erff(v0 * 0.70710678118654752f));
                    float q1 = 0.5f * v1 * (1.0f + erff(v1 * 0.70710678118654752f));
                    *(__half2*)(g_Hh + slot * HDIM + gc) = __floats2half2_rn(q0, q1);
                } else if (lrow < cnt) {
                    red_add_v2(out + (size_t)tok[hh] * CDIM + gc, gt[hh] * v0, gt[hh] * v1);
                }
            }
        }
    }
}

// ---------------------------------------------------------------------------
__global__ void loss_kernel(float* __restrict__ out, int out_size) {
    if (threadIdx.x == 0 && out_size > T_TOK * CDIM) {
        float l = 0.0f;
#pragma unroll
        for (int e = 0; e < EDIM; e++) {
            float m = g_gate_sums[e] / (float)T_TOK;
            l += m * logf(m + 1e-8f);
        }
        out[T_TOK * CDIM] = l;
    }
}

// ---------------------------------------------------------------------------
extern "C" void kernel_launch(void* const* d_in, const int* in_sizes, int n_in,
                              void* d_out, int out_size) {
    const float* x      = (const float*)d_in[0];
    const float* gumbel = (const float*)d_in[1];
    const float* gate_w = (const float*)d_in[2];
    const float* gate_b = (const float*)d_in[3];
    const float* w1     = (const float*)d_in[4];
    const float* b1     = (const float*)d_in[5];
    const float* w2     = (const float*)d_in[6];
    const float* b2     = (const float*)d_in[7];
    float* out = (float*)d_out;

    static cudaStream_t s1 = nullptr, s2 = nullptr;
    static cudaEvent_t evFork, evW1, evW2;
    if (!s1) {
        cudaStreamCreateWithFlags(&s1, cudaStreamNonBlocking);
        cudaStreamCreateWithFlags(&s2, cudaStreamNonBlocking);
        cudaEventCreateWithFlags(&evFork, cudaEventDisableTiming);
        cudaEventCreateWithFlags(&evW1, cudaEventDisableTiming);
        cudaEventCreateWithFlags(&evW2, cudaEventDisableTiming);
        cudaFuncSetAttribute(gemm_hmma<true, 16>,
                             cudaFuncAttributeMaxDynamicSharedMemorySize, GEMM_SMEM);
        cudaFuncSetAttribute(gemm_hmma<false, 64>,
                             cudaFuncAttributeMaxDynamicSharedMemorySize, GEMM_SMEM);
    }

    // Fork: convert_w1 on s1, convert_w2 on s2, gate/zero on main stream.
    cudaEventRecord(evFork, 0);
    cudaStreamWaitEvent(s1, evFork, 0);
    cudaStreamWaitEvent(s2, evFork, 0);

    convert_w_kernel<<<dim3(HDIM / 32, CDIM / 64, EDIM), 256, 0, s1>>>(w1, CDIM, HDIM, 0);
    cudaEventRecord(evW1, s1);
    convert_w_kernel<<<dim3(CDIM / 32, HDIM / 64, EDIM), 256, 0, s2>>>(w2, HDIM, CDIM, 1);
    cudaEventRecord(evW2, s2);

    zero_out_kernel<<<T_TOK, 256>>>(out);
    gate_kernel<<<T_TOK / 8, 256>>>(x, gumbel, gate_w, gate_b);

    // Join w1 before GEMM1, w2 before GEMM2.
    cudaStreamWaitEvent(0, evW1, 0);
    gemm_hmma<true, 16><<<dim3(HDIM / 128, T_TOK / 128, EDIM), 128, GEMM_SMEM>>>(b1, out);
    cudaStreamWaitEvent(0, evW2, 0);
    gemm_hmma<false, 64><<<dim3(CDIM / 128, T_TOK / 128, EDIM), 128, GEMM_SMEM>>>(b2, out);
    loss_kernel<<<1, 32>>>(out, out_size);
}

// round 14
// speedup vs baseline: 1.4319x; 1.0908x over previous
#include <cuda_runtime.h>
#include <cuda_fp16.h>
#include <math.h>
#include <stdint.h>

#define T_TOK 4096
#define CDIM  1024
#define HDIM  4096
#define EDIM  8
#define GATE_WARPS 16

// ---------------- device scratch (allocation-free) ----------------
__device__ float  g_gate_sums[EDIM];
__device__ int    g_cnt[EDIM];
__device__ int    g_bucket_tok[EDIM * T_TOK];
__device__ float  g_slot_gate[EDIM * T_TOK];
__device__ __half g_Ah [(size_t)EDIM * T_TOK * CDIM];   // gathered x, fp16
__device__ __half g_Hh [(size_t)EDIM * T_TOK * HDIM];   // gelu(h), fp16
__device__ __half g_W1t[(size_t)EDIM * HDIM  * CDIM];   // w1^T fp16 [E][H][C]
__device__ __half g_W2t[(size_t)EDIM * CDIM  * HDIM];   // w2^T fp16 [E][C][H]

// ---------------- helpers ----------------
__device__ __forceinline__ uint32_t smem_u32(const void* p) {
    uint32_t a;
    asm("{ .reg .u64 t; cvta.to.shared.u64 t, %1; cvt.u32.u64 %0, t; }" : "=r"(a) : "l"(p));
    return a;
}
__device__ __forceinline__ void cp_async16(uint32_t dst, const void* src) {
    asm volatile("cp.async.cg.shared.global [%0], [%1], 16;\n" :: "r"(dst), "l"(src));
}
#define CP_COMMIT() asm volatile("cp.async.commit_group;" ::: "memory")
#define CP_WAIT1()  asm volatile("cp.async.wait_group 1;" ::: "memory")

__device__ __forceinline__ void ldmx4(uint32_t& r0, uint32_t& r1, uint32_t& r2, uint32_t& r3,
                                      uint32_t addr) {
    asm volatile("ldmatrix.sync.aligned.m8n8.x4.shared.b16 {%0,%1,%2,%3}, [%4];"
                 : "=r"(r0), "=r"(r1), "=r"(r2), "=r"(r3) : "r"(addr));
}
__device__ __forceinline__ void mma16816(float* d, const uint32_t* a, uint32_t b0, uint32_t b1) {
    asm volatile("mma.sync.aligned.m16n8k16.row.col.f32.f16.f16.f32 "
                 "{%0,%1,%2,%3}, {%4,%5,%6,%7}, {%8,%9}, {%0,%1,%2,%3};"
                 : "+f"(d[0]), "+f"(d[1]), "+f"(d[2]), "+f"(d[3])
                 : "r"(a[0]), "r"(a[1]), "r"(a[2]), "r"(a[3]), "r"(b0), "r"(b1));
}
__device__ __forceinline__ void red_add_v2(float* ptr, float a, float b) {
    asm volatile("red.global.add.v2.f32 [%0], {%1, %2};"
                 :: "l"(ptr), "f"(a), "f"(b) : "memory");
}
// byte offset in a [rows][64 halves] (128B-row) tile; full SW128 8-phase swizzle
__device__ __forceinline__ uint32_t sma64(int r, int c) {
    return (uint32_t)(((r << 3) | (c ^ (r & 7))) << 4);
}

// ---------------------------------------------------------------------------
// zero out + init counters
__global__ void zero_out_kernel(float* __restrict__ out) {
    size_t i = (size_t)blockIdx.x * blockDim.x + threadIdx.x;
    ((float4*)out)[i] = make_float4(0.f, 0.f, 0.f, 0.f);
    if (blockIdx.x == 0 && threadIdx.x < EDIM) {
        g_gate_sums[threadIdx.x] = 0.0f;
        g_cnt[threadIdx.x] = 0;
    }
}

// One warp per token; 16 tokens per block. Block-aggregated atomics:
// one atomicAdd per expert per block for gate_sums and for g_cnt.
__global__ __launch_bounds__(512) void gate_kernel(const float* __restrict__ x,
                                                   const float* __restrict__ gumbel,
                                                   const float* __restrict__ gw,
                                                   const float* __restrict__ gb) {
    const int warp = threadIdx.x >> 5, lane = threadIdx.x & 31;
    const int t = blockIdx.x * GATE_WARPS + warp;
    const float* xr = x + (size_t)t * CDIM;

    __shared__ float s_g[GATE_WARPS][EDIM];
    __shared__ int   s_i0[GATE_WARPS], s_i1[GATE_WARPS];
    __shared__ int   s_base[EDIM];

    float2 xv[16];
    float acc[EDIM];
#pragma unroll
    for (int e = 0; e < EDIM; e++) acc[e] = 0.0f;
#pragma unroll
    for (int i = 0; i < 16; i++) {
        int col = i * 64 + lane * 2;
        xv[i] = *(const float2*)(xr + col);
        float4 w0 = *(const float4*)(gw + (size_t)col * 8);
        float4 w1v = *(const float4*)(gw + (size_t)col * 8 + 4);
        float4 w2v = *(const float4*)(gw + (size_t)col * 8 + 8);
        float4 w3v = *(const float4*)(gw + (size_t)col * 8 + 12);
        acc[0] += xv[i].x * w0.x + xv[i].y * w2v.x;
        acc[1] += xv[i].x * w0.y + xv[i].y * w2v.y;
        acc[2] += xv[i].x * w0.z + xv[i].y * w2v.z;
        acc[3] += xv[i].x * w0.w + xv[i].y * w2v.w;
        acc[4] += xv[i].x * w1v.x + xv[i].y * w3v.x;
        acc[5] += xv[i].x * w1v.y + xv[i].y * w3v.y;
        acc[6] += xv[i].x * w1v.z + xv[i].y * w3v.z;
        acc[7] += xv[i].x * w1v.w + xv[i].y * w3v.w;
    }
#pragma unroll
    for (int off = 16; off; off >>= 1) {
#pragma unroll
        for (int e = 0; e < EDIM; e++)
            acc[e] += __shfl_xor_sync(0xffffffffu, acc[e], off);
    }

    float l[EDIM]; float mx = -1e30f;
#pragma unroll
    for (int e = 0; e < EDIM; e++) {
        l[e] = acc[e] + gb[e] + gumbel[t * EDIM + e];
        mx = fmaxf(mx, l[e]);
    }
    float sum = 0.0f;
#pragma unroll
    for (int e = 0; e < EDIM; e++) { l[e] = expf(l[e] - mx); sum += l[e]; }
    float inv = 1.0f / sum;
    float g[EDIM];
#pragma unroll
    for (int e = 0; e < EDIM; e++) g[e] = l[e] * inv;
    int i0 = 0;
#pragma unroll
    for (int e = 1; e < EDIM; e++) if (g[e] > g[i0]) i0 = e;
    int i1 = (i0 == 0) ? 1 : 0;
#pragma unroll
    for (int e = 0; e < EDIM; e++) if (e != i0 && g[e] > g[i1]) i1 = e;

    if (lane == 0) {
        s_i0[warp] = i0; s_i1[warp] = i1;
#pragma unroll
        for (int e = 0; e < EDIM; e++) s_g[warp][e] = g[e];
    }
    __syncthreads();

    if (threadIdx.x < EDIM) {
        const int e = threadIdx.x;
        float gs = 0.0f; int cnt = 0;
#pragma unroll
        for (int wv = 0; wv < GATE_WARPS; wv++) {
            gs += s_g[wv][e];
            cnt += (s_i0[wv] == e) + (s_i1[wv] == e);
        }
        atomicAdd(&g_gate_sums[e], gs);
        s_base[e] = cnt ? atomicAdd(&g_cnt[e], cnt) : 0;
    }
    __syncthreads();

    // in-block rank for this warp's two picks (i0 != i1 always)
    int r0 = 0, r1 = 0;
#pragma unroll
    for (int wv = 0; wv < GATE_WARPS; wv++) {
        if (wv < warp) {
            r0 += (s_i0[wv] == i0) + (s_i1[wv] == i0);
            r1 += (s_i0[wv] == i1) + (s_i1[wv] == i1);
        }
    }
    const int p0 = s_base[i0] + r0;
    const int p1 = s_base[i1] + r1;

    if (lane == 0) {
        g_bucket_tok[i0 * T_TOK + p0] = t;
        g_slot_gate[i0 * T_TOK + p0] = g[i0];
        g_bucket_tok[i1 * T_TOK + p1] = t;
        g_slot_gate[i1 * T_TOK + p1] = g[i1];
    }

    __half* d0 = g_Ah + (size_t)(i0 * T_TOK + p0) * CDIM;
    __half* d1 = g_Ah + (size_t)(i1 * T_TOK + p1) * CDIM;
#pragma unroll
    for (int i = 0; i < 16; i++) {
        int col = i * 64 + lane * 2;
        __half2 h = __floats2half2_rn(xv[i].x, xv[i].y);
        *(__half2*)(d0 + col) = h;
        *(__half2*)(d1 + col) = h;
    }
}

// transpose + fp16 convert: in [E][A][Bd] fp32 -> out [E][Bd][A] fp16
__global__ void convert_w_kernel(const float* __restrict__ W, int A, int Bd, int which) {
    __shared__ float s[64][33];
    const int e = blockIdx.z;
    const int a0 = blockIdx.y * 64, b0 = blockIdx.x * 32;
    const int t = threadIdx.x;  // 256
    const float* Wp = W + (size_t)e * A * Bd;
    __half* Wt = (which ? g_W2t : g_W1t) + (size_t)e * A * Bd;
    {
        const int col = t & 31;
        const int r0 = t >> 5;
#pragma unroll
        for (int i = 0; i < 8; i++) {
            int r = r0 + i * 8;
            s[r][col] = Wp[(size_t)(a0 + r) * Bd + b0 + col];
        }
    }
    __syncthreads();
    {
        const int col2 = t & 31;
        const int bb0  = t >> 5;
#pragma unroll
        for (int j = 0; j < 4; j++) {
            int b = bb0 + j * 8;
            __half2 hv = __floats2half2_rn(s[2 * col2][b], s[2 * col2 + 1][b]);
            *(__half2*)(Wt + (size_t)(b0 + b) * A + a0 + 2 * col2) = hv;
        }
    }
}

// ---------------------------------------------------------------------------
// HMMA grouped GEMM: BM=128, BN=128, BK=64, 128 threads (4 warps, 64x64 tiles).
#define GEMM_SMEM (3 * 32768)
template<bool GELU, int NK>   // NK = K/64
__global__ __launch_bounds__(128, 2) void gemm_hmma(const float* __restrict__ bias,
                                                    float* __restrict__ out) {
    const int e = blockIdx.z;
    const int cnt = g_cnt[e];
    const int m0 = blockIdx.y * 128;
    if (m0 >= cnt) return;
    const int n0 = blockIdx.x * 128;

    const int K    = GELU ? CDIM : HDIM;
    const int NTOT = GELU ? HDIM : CDIM;
    const __half* __restrict__ abase = GELU ? g_Ah  : g_Hh;
    const __half* __restrict__ bbase = GELU ? g_W1t : g_W2t;

    extern __shared__ __align__(16) char smraw[];
    const uint32_t sb = smem_u32(smraw);

    const int tid  = threadIdx.x;
    const int lane = tid & 31;
    const int w    = tid >> 5;
    const int wm   = w & 1;
    const int wn   = w >> 1;

    const __half* A0 = abase + (size_t)(e * T_TOK + m0) * K;
    const __half* B0 = bbase + ((size_t)e * NTOT + n0) * K;

    float acc[4][8][4];
#pragma unroll
    for (int i = 0; i < 4; i++)
#pragma unroll
        for (int j = 0; j < 8; j++)
#pragma unroll
            for (int q = 0; q < 4; q++) acc[i][j][q] = 0.0f;

    auto load_stage = [&](int kc) {
        const int st = kc % 3;
        const __half* ap = A0 + kc * 64;
        const __half* bp = B0 + kc * 64;
        const uint32_t aS = sb + st * 32768;
        const uint32_t bS = aS + 16384;
#pragma unroll
        for (int h = 0; h < 8; h++) {
            int id = tid + h * 128;
            int row = id >> 3, c = id & 7;
            cp_async16(aS + sma64(row, c), ap + (size_t)row * K + c * 8);
        }
#pragma unroll
        for (int h = 0; h < 8; h++) {
            int id = tid + h * 128;
            int row = id >> 3, c = id & 7;
            cp_async16(bS + sma64(row, c), bp + (size_t)row * K + c * 8);
        }
    };

    load_stage(0); CP_COMMIT();
    load_stage(1); CP_COMMIT();

#pragma unroll 1
    for (int kc = 0; kc < NK; kc++) {
        const int s = kc % 3;
        CP_WAIT1();
        __syncthreads();
        if (kc + 2 < NK) load_stage(kc + 2);
        CP_COMMIT();

        const uint32_t aS = sb + s * 32768;
        const uint32_t bS = aS + 16384;
#pragma unroll
        for (int ks = 0; ks < 4; ks++) {
            uint32_t afr[4][4];
#pragma unroll
            for (int mi = 0; mi < 4; mi++) {
                int row = wm * 64 + mi * 16 + ((lane >> 3) & 1) * 8 + (lane & 7);
                int ch  = ks * 2 + (lane >> 4);
                ldmx4(afr[mi][0], afr[mi][1], afr[mi][2], afr[mi][3], aS + sma64(row, ch));
            }
            uint32_t bfr[4][4];
#pragma unroll
            for (int nj = 0; nj < 4; nj++) {
                int row = wn * 64 + nj * 16 + (lane >> 4) * 8 + (lane & 7);
                int ch  = ks * 2 + ((lane >> 3) & 1);
                ldmx4(bfr[nj][0], bfr[nj][1], bfr[nj][2], bfr[nj][3], bS + sma64(row, ch));
            }
#pragma unroll
            for (int mi = 0; mi < 4; mi++)
#pragma unroll
                for (int nj = 0; nj < 4; nj++) {
                    mma16816(acc[mi][nj * 2 + 0], afr[mi], bfr[nj][0], bfr[nj][1]);
                    mma16816(acc[mi][nj * 2 + 1], afr[mi], bfr[nj][2], bfr[nj][3]);
                }
        }
        __syncthreads();
    }

    // ---- epilogue ----
    const int r0l = lane >> 2;
    const int c0l = (lane & 3) * 2;
#pragma unroll
    for (int mi = 0; mi < 4; mi++) {
        int   tok[2];
        float gt[2];
#pragma unroll
        for (int hh = 0; hh < 2; hh++) {
            int lrow = m0 + wm * 64 + mi * 16 + r0l + hh * 8;
            if (!GELU && lrow < cnt) {
                tok[hh] = g_bucket_tok[e * T_TOK + lrow];
                gt[hh]  = g_slot_gate[e * T_TOK + lrow];
            } else {
                tok[hh] = 0; gt[hh] = 0.f;
            }
        }
#pragma unroll
        for (int ni = 0; ni < 8; ni++) {
            int gc = n0 + wn * 64 + ni * 8 + c0l;
            float bv0 = __ldg(&bias[(size_t)e * NTOT + gc]);
            float bv1 = __ldg(&bias[(size_t)e * NTOT + gc + 1]);
#pragma unroll
            for (int hh = 0; hh < 2; hh++) {
                int lrow = m0 + wm * 64 + mi * 16 + r0l + hh * 8;
                float v0 = acc[mi][ni][hh * 2 + 0] + bv0;
                float v1 = acc[mi][ni][hh * 2 + 1] + bv1;
                if (GELU) {
                    size_t slot = (size_t)(e * T_TOK) + lrow;
                    float q0 = 0.5f * v0 * (1.0f + erff(v0 * 0.70710678118654752f));
                    float q1 = 0.5f * v1 * (1.0f + erff(v1 * 0.70710678118654752f));
                    *(__half2*)(g_Hh + slot * HDIM + gc) = __floats2half2_rn(q0, q1);
                } else if (lrow < cnt) {
                    red_add_v2(out + (size_t)tok[hh] * CDIM + gc, gt[hh] * v0, gt[hh] * v1);
                }
            }
        }
    }
}

// ---------------------------------------------------------------------------
__global__ void loss_kernel(float* __restrict__ out, int out_size) {
    if (threadIdx.x == 0 && out_size > T_TOK * CDIM) {
        float l = 0.0f;
#pragma unroll
        for (int e = 0; e < EDIM; e++) {
            float m = g_gate_sums[e] / (float)T_TOK;
            l += m * logf(m + 1e-8f);
        }
        out[T_TOK * CDIM] = l;
    }
}

// ---------------------------------------------------------------------------
extern "C" void kernel_launch(void* const* d_in, const int* in_sizes, int n_in,
                              void* d_out, int out_size) {
    const float* x      = (const float*)d_in[0];
    const float* gumbel = (const float*)d_in[1];
    const float* gate_w = (const float*)d_in[2];
    const float* gate_b = (const float*)d_in[3];
    const float* w1     = (const float*)d_in[4];
    const float* b1     = (const float*)d_in[5];
    const float* w2     = (const float*)d_in[6];
    const float* b2     = (const float*)d_in[7];
    float* out = (float*)d_out;

    static cudaStream_t s1 = nullptr, s2 = nullptr;
    static cudaEvent_t evFork, evGate, evW1, evW2;
    if (!s1) {
        cudaStreamCreateWithFlags(&s1, cudaStreamNonBlocking);
        cudaStreamCreateWithFlags(&s2, cudaStreamNonBlocking);
        cudaEventCreateWithFlags(&evFork, cudaEventDisableTiming);
        cudaEventCreateWithFlags(&evGate, cudaEventDisableTiming);
        cudaEventCreateWithFlags(&evW1, cudaEventDisableTiming);
        cudaEventCreateWithFlags(&evW2, cudaEventDisableTiming);
        cudaFuncSetAttribute(gemm_hmma<true, 16>,
                             cudaFuncAttributeMaxDynamicSharedMemorySize, GEMM_SMEM);
        cudaFuncSetAttribute(gemm_hmma<false, 64>,
                             cudaFuncAttributeMaxDynamicSharedMemorySize, GEMM_SMEM);
    }

    // Fork: convert_w1 on s1 concurrent with {zero, gate} on main.
    cudaEventRecord(evFork, 0);
    cudaStreamWaitEvent(s1, evFork, 0);
    convert_w_kernel<<<dim3(HDIM / 32, CDIM / 64, EDIM), 256, 0, s1>>>(w1, CDIM, HDIM, 0);
    cudaEventRecord(evW1, s1);

    zero_out_kernel<<<T_TOK, 256>>>(out);
    gate_kernel<<<T_TOK / GATE_WARPS, 512>>>(x, gumbel, gate_w, gate_b);
    cudaEventRecord(evGate, 0);

    // convert_w2 runs in GEMM1's shadow (starts after gate, overlaps GEMM1).
    cudaStreamWaitEvent(s2, evGate, 0);
    convert_w_kernel<<<dim3(CDIM / 32, HDIM / 64, EDIM), 256, 0, s2>>>(w2, HDIM, CDIM, 1);
    cudaEventRecord(evW2, s2);

    cudaStreamWaitEvent(0, evW1, 0);
    gemm_hmma<true, 16><<<dim3(HDIM / 128, T_TOK / 128, EDIM), 128, GEMM_SMEM>>>(b1, out);
    cudaStreamWaitEvent(0, evW2, 0);
    gemm_hmma<false, 64><<<dim3(CDIM / 128, T_TOK / 128, EDIM), 128, GEMM_SMEM>>>(b2, out);
    loss_kernel<<<1, 32>>>(out, out_size);
}